// round 11
// baseline (speedup 1.0000x reference)
#include <cuda_runtime.h>
#include <cstdint>
#include <cstdlib>

// Eager module loading: __device__ globals allocated at context init.
__attribute__((constructor)) static void _force_eager_loading() {
    setenv("CUDA_MODULE_LOADING", "EAGER", 1);
}

#define NN     2048
#define TT     512
#define ROWS_C (NN*TT)        /* 1048576 */
#define ER_C   (NN*(TT-1))    /* 1046528 */
#define RPB    256            /* rows per block: 8 warps x 32 rows */
#define NBLK   (ROWS_C/RPB)   /* 4096 */
#define BN_EPS 1e-5

typedef unsigned long long u64;

// K1 smem float offsets:
//   weights 0..3776 (W1,b10,W2,b2,W3,b3,WC,b1p,b1m)
//   xT 3776..8384 (8 warps x 576: [k][row] stride 36, 33 rows)
//   A   8384..26816 (8 warps x 2304: duplicated [col][row-pair] stride 72)
//   WS 26816..28352
#define E_XT   3776
#define E_A    8384
#define E_WS   26816
#define E_TOT  28352          /* 113408 B */
// K2 smem float offsets
#define N_A    3360
#define N_WS   21792
#define N_TOT  22304          /* 89216 B */

// ---- device scratch ----
__device__ float g_cf[(size_t)ER_C * 32];   // fwd pre-BN cache (134 MB)
__device__ float g_cb[(size_t)ER_C * 32];   // bwd pre-BN cache (134 MB)
__device__ float g_epart[3][2][32][NBLK];
__device__ float g_npart[2][32][NBLK];
__device__ float g_escale[3][32], g_ebias[3][32];
__device__ float g_nscale[32],    g_nbias[32];

// ---- packed f32x2 helpers ----
__device__ __forceinline__ u64 pk(float x, float y) {
    u64 d; asm("mov.b64 %0, {%1, %2};" : "=l"(d) : "f"(x), "f"(y)); return d;
}
__device__ __forceinline__ void upk(u64 v, float& lo, float& hi) {
    asm("mov.b64 {%0, %1}, %2;" : "=f"(lo), "=f"(hi) : "l"(v));
}
__device__ __forceinline__ u64 fma2(u64 a, u64 b, u64 c) {
    u64 d; asm("fma.rn.f32x2 %0, %1, %2, %3;" : "=l"(d) : "l"(a), "l"(b), "l"(c)); return d;
}
__device__ __forceinline__ float lrelu(float x) { return fmaxf(x, 0.01f * x); }

// accumulate 4 pre-packed row-activations (dup pairs) against one weight row
__device__ __forceinline__ void accum_dup(const u64* __restrict__ wrow, int c_g,
                                          u64 x0, u64 x1, u64 x2, u64 x3, u64* h) {
    ulonglong2 wA = *reinterpret_cast<const ulonglong2*>(wrow + c_g * 4);
    ulonglong2 wB = *reinterpret_cast<const ulonglong2*>(wrow + c_g * 4 + 2);
    h[0]  = fma2(x0, wA.x, h[0]);  h[1]  = fma2(x0, wA.y, h[1]);
    h[2]  = fma2(x0, wB.x, h[2]);  h[3]  = fma2(x0, wB.y, h[3]);
    h[4]  = fma2(x1, wA.x, h[4]);  h[5]  = fma2(x1, wA.y, h[5]);
    h[6]  = fma2(x1, wB.x, h[6]);  h[7]  = fma2(x1, wB.y, h[7]);
    h[8]  = fma2(x2, wA.x, h[8]);  h[9]  = fma2(x2, wA.y, h[9]);
    h[10] = fma2(x2, wB.x, h[10]); h[11] = fma2(x2, wB.y, h[11]);
    h[12] = fma2(x3, wA.x, h[12]); h[13] = fma2(x3, wA.y, h[13]);
    h[14] = fma2(x3, wB.x, h[14]); h[15] = fma2(x3, wB.y, h[15]);
}

// scalar-activation variant (L1 paths reading xT)
__device__ __forceinline__ void accum_row(const u64* __restrict__ wrow, int c_g,
                                          float a0, float a1, float a2, float a3, u64* h) {
    accum_dup(wrow, c_g, pk(a0, a0), pk(a1, a1), pk(a2, a2), pk(a3, a3), h);
}

// 32x32 GEMM layer: A staged duplicated [col-k][row-pair] stride 72
__device__ __forceinline__ void gemm32(const float* __restrict__ As,
                                       const u64* __restrict__ W, const u64* __restrict__ B,
                                       int r_g, int c_g, u64* h) {
#pragma unroll
    for (int cp = 0; cp < 4; cp++) {
        u64 v = B[c_g * 4 + cp];
        h[cp] = v; h[4 + cp] = v; h[8 + cp] = v; h[12 + cp] = v;
    }
#pragma unroll 4
    for (int k = 0; k < 32; k++) {
        const u64* ap = reinterpret_cast<const u64*>(As + k * 72 + 8 * r_g);
        ulonglong2 a01 = *reinterpret_cast<const ulonglong2*>(ap);
        ulonglong2 a23 = *reinterpret_cast<const ulonglong2*>(ap + 2);
        accum_dup(W + k * 16, c_g, a01.x, a01.y, a23.x, a23.y, h);
    }
}

__device__ __forceinline__ void unpack_tile(const u64* h, float o[4][8], bool relu) {
#pragma unroll
    for (int r = 0; r < 4; r++)
#pragma unroll
        for (int cp = 0; cp < 4; cp++) {
            float lo, hi; upk(h[r * 4 + cp], lo, hi);
            o[r][2 * cp]     = relu ? lrelu(lo) : lo;
            o[r][2 * cp + 1] = relu ? lrelu(hi) : hi;
        }
}

// store lane tile transposed + duplicated into A buffer ([col][row-pair] stride 72)
__device__ __forceinline__ void stage_tile(float* As, int r_g, int c_g, const float o[4][8]) {
    __syncwarp();
#pragma unroll
    for (int cc = 0; cc < 8; cc++) {
        float* p = As + (8 * c_g + cc) * 72 + 8 * r_g;
        *reinterpret_cast<float4*>(p)     = make_float4(o[0][cc], o[0][cc], o[1][cc], o[1][cc]);
        *reinterpret_cast<float4*>(p + 4) = make_float4(o[2][cc], o[2][cc], o[3][cc], o[3][cc]);
    }
    __syncwarp();
}

// L2 + L3 of a 3-layer MLP (h holds L1 pre-act on entry)
__device__ __forceinline__ void mlp_tail(float* As,
                                         const u64* W2, const u64* B2,
                                         const u64* W3, const u64* B3,
                                         int r_g, int c_g, u64* h) {
    float o[4][8];
    unpack_tile(h, o, true);
    stage_tile(As, r_g, c_g, o);
    gemm32(As, W2, B2, r_g, c_g, h);
    unpack_tile(h, o, true);
    stage_tile(As, r_g, c_g, o);
    gemm32(As, W3, B3, r_g, c_g, h);
}

// edge layer-1: two 16-wide segments from xT (stride 36); dir prefolded into bias
template<bool PA, bool QA>
__device__ __forceinline__ void edge_L1(const float* __restrict__ xTw, int po, int qo,
                                        const u64* __restrict__ W1, const u64* __restrict__ B1v,
                                        int r_g, int c_g, u64* h) {
#pragma unroll
    for (int cp = 0; cp < 4; cp++) {
        u64 v = B1v[c_g * 4 + cp];
        h[cp] = v; h[4 + cp] = v; h[8 + cp] = v; h[12 + cp] = v;
    }
#pragma unroll 4
    for (int k = 0; k < 16; k++) {
        const float* p = xTw + k * 36 + 4 * r_g + po;
        float a0, a1, a2, a3;
        if (PA) { float4 t = *reinterpret_cast<const float4*>(p); a0 = t.x; a1 = t.y; a2 = t.z; a3 = t.w; }
        else    { a0 = p[0]; a1 = p[1]; a2 = p[2]; a3 = p[3]; }
        accum_row(W1 + k * 16, c_g, a0, a1, a2, a3, h);
    }
#pragma unroll 4
    for (int k = 0; k < 16; k++) {
        const float* p = xTw + k * 36 + 4 * r_g + qo;
        float a0, a1, a2, a3;
        if (QA) { float4 t = *reinterpret_cast<const float4*>(p); a0 = t.x; a1 = t.y; a2 = t.z; a3 = t.w; }
        else    { a0 = p[0]; a1 = p[1]; a2 = p[2]; a3 = p[3]; }
        accum_row(W1 + (16 + k) * 16, c_g, a0, a1, a2, a3, h);
    }
}

// inplace edge layer-1 with combined weights (p==q): 16 k-steps
__device__ __forceinline__ void edge_L1_inplace(const float* __restrict__ xTw,
                                                const u64* __restrict__ WC, const u64* __restrict__ B1,
                                                int r_g, int c_g, u64* h) {
#pragma unroll
    for (int cp = 0; cp < 4; cp++) {
        u64 v = B1[c_g * 4 + cp];
        h[cp] = v; h[4 + cp] = v; h[8 + cp] = v; h[12 + cp] = v;
    }
#pragma unroll 4
    for (int k = 0; k < 16; k++) {
        float4 t = *reinterpret_cast<const float4*>(xTw + k * 36 + 4 * r_g);
        accum_row(WC + k * 16, c_g, t.x, t.y, t.z, t.w, h);
    }
}

// per-warp masked per-channel sum/sumsq -> ws[warp][c]
__device__ __forceinline__ void warp_stats(const float o[4][8], const float m[4],
                                           int lane, int c_g, float* wsS, float* wsQ) {
    float s[8], q[8];
#pragma unroll
    for (int cc = 0; cc < 8; cc++) { s[cc] = 0.f; q[cc] = 0.f; }
#pragma unroll
    for (int r = 0; r < 4; r++)
#pragma unroll
        for (int cc = 0; cc < 8; cc++) {
            float v = o[r][cc] * m[r];
            s[cc] += v; q[cc] += v * v;
        }
#pragma unroll
    for (int msk = 4; msk <= 16; msk <<= 1)
#pragma unroll
        for (int cc = 0; cc < 8; cc++) {
            s[cc] += __shfl_xor_sync(0xffffffffu, s[cc], msk);
            q[cc] += __shfl_xor_sync(0xffffffffu, q[cc], msk);
        }
    if (lane < 4) {
#pragma unroll
        for (int cc = 0; cc < 8; cc++) { wsS[8 * c_g + cc] = s[cc]; wsQ[8 * c_g + cc] = q[cc]; }
    }
}

__device__ __forceinline__ void store_tile_gmem(float* __restrict__ dout, int r0,
                                                int r_g, int c_g, const float o[4][8]) {
#pragma unroll
    for (int rr = 0; rr < 4; rr++) {
        float4* p = reinterpret_cast<float4*>(dout) + (size_t)(r0 + 4 * r_g + rr) * 8 + c_g * 2;
        p[0] = make_float4(o[rr][0], o[rr][1], o[rr][2], o[rr][3]);
        p[1] = make_float4(o[rr][4], o[rr][5], o[rr][6], o[rr][7]);
    }
}

// store lane tile to edge cache [e][32], e = r - n; skip rows with t==511
__device__ __forceinline__ void store_tile_cache(float* __restrict__ dst, int r0,
                                                 int r_g, int c_g, const float o[4][8]) {
#pragma unroll
    for (int rr = 0; rr < 4; rr++) {
        int r = r0 + 4 * r_g + rr;
        if ((r & 511) != 511) {
            int e = r - (r >> 9);
            float4* p = reinterpret_cast<float4*>(dst + (size_t)e * 32 + 8 * c_g);
            p[0] = make_float4(o[rr][0], o[rr][1], o[rr][2], o[rr][3]);
            p[1] = make_float4(o[rr][4], o[rr][5], o[rr][6], o[rr][7]);
        }
    }
}

// ---------------- K1: 3 edge chains; inplace -> dout, fwd/bwd -> caches; stats ----------------
__global__ __launch_bounds__(256, 2) void k_edge(
    const float* __restrict__ x, float* __restrict__ dout,
    const float* __restrict__ eW1, const float* __restrict__ eb1,
    const float* __restrict__ eW2, const float* __restrict__ eb2,
    const float* __restrict__ eW3, const float* __restrict__ eb3)
{
    extern __shared__ float sm[];
    const int tid = threadIdx.x, bid = blockIdx.x;
    for (int i = tid; i < 3776; i += 256) {
        float v;
        if      (i < 1056) v = eW1[i];
        else if (i < 1088) v = eb1[i - 1056];
        else if (i < 2112) v = eW2[i - 1088];
        else if (i < 2144) v = eb2[i - 2112];
        else if (i < 3168) v = eW3[i - 2144];
        else if (i < 3200) v = eb3[i - 3168];
        else if (i < 3712) {                     // WC = W1_p + W1_q
            int k = (i - 3200) >> 5, j = (i - 3200) & 31;
            v = eW1[k * 32 + j] + eW1[(k + 16) * 32 + j];
        }
        else if (i < 3744) v = eb1[i - 3712] + eW1[1024 + (i - 3712)];   // b1p
        else               v = eb1[i - 3744] - eW1[1024 + (i - 3744)];   // b1m
        sm[i] = v;
    }
    for (int idx = tid; idx < 8 * 528; idx += 256) {
        int w = idx / 528, rem = idx - w * 528;
        int k = rem & 15, i = rem >> 4;
        int row = bid * 256 + w * 32 + i;
        if (row > ROWS_C - 1) row = ROWS_C - 1;
        sm[E_XT + w * 576 + k * 36 + i] = x[(size_t)row * 16 + k];
    }
    __syncthreads();

    const u64* W1  = (const u64*)(sm);
    const u64* B1  = (const u64*)(sm + 1056);
    const u64* W2  = (const u64*)(sm + 1088);
    const u64* B2  = (const u64*)(sm + 2112);
    const u64* W3  = (const u64*)(sm + 2144);
    const u64* B3  = (const u64*)(sm + 3168);
    const u64* WC  = (const u64*)(sm + 3200);
    const u64* B1p = (const u64*)(sm + 3712);
    const u64* B1m = (const u64*)(sm + 3744);

    int lane = tid & 31, warp = tid >> 5;
    int r_g = lane >> 2, c_g = lane & 3;
    const float* xTw = sm + E_XT + warp * 576;
    float* Asw = sm + E_A + warp * 2304;
    int r0 = bid * 256 + warp * 32;

    float mk[4], mall[4];
#pragma unroll
    for (int rr = 0; rr < 4; rr++) {
        mall[rr] = 1.f;
        mk[rr] = (((r0 + 4 * r_g + rr) & 511) != 511) ? 1.f : 0.f;
    }

    u64 h[16];
    float o[4][8];

    // inplace: [x_t, x_t, 0]
    edge_L1_inplace(xTw, WC, B1, r_g, c_g, h);
    mlp_tail(Asw, W2, B2, W3, B3, r_g, c_g, h);
    unpack_tile(h, o, false);
    store_tile_gmem(dout, r0, r_g, c_g, o);
    warp_stats(o, mall, lane, c_g, sm + E_WS + (0 * 8 + warp) * 32, sm + E_WS + (1 * 8 + warp) * 32);

    // fwd edge (t, t+1): [x_{t+1}, x_t, +1] -> p off 1 (scalar), q off 0 (vec); dir in b1p
    edge_L1<false, true>(xTw, 1, 0, W1, B1p, r_g, c_g, h);
    mlp_tail(Asw, W2, B2, W3, B3, r_g, c_g, h);
    unpack_tile(h, o, false);
    store_tile_cache(g_cf, r0, r_g, c_g, o);
    warp_stats(o, mk, lane, c_g, sm + E_WS + (2 * 8 + warp) * 32, sm + E_WS + (3 * 8 + warp) * 32);

    // bwd edge (t, t+1): [x_t, x_{t+1}, -1] -> p off 0 (vec), q off 1 (scalar); dir in b1m
    edge_L1<true, false>(xTw, 0, 1, W1, B1m, r_g, c_g, h);
    mlp_tail(Asw, W2, B2, W3, B3, r_g, c_g, h);
    unpack_tile(h, o, false);
    store_tile_cache(g_cb, r0, r_g, c_g, o);
    warp_stats(o, mk, lane, c_g, sm + E_WS + (4 * 8 + warp) * 32, sm + E_WS + (5 * 8 + warp) * 32);

    __syncthreads();
    if (tid < 192) {
        int chain = tid / 64, st = (tid >> 5) & 1, c = tid & 31;
        float a = 0.f;
#pragma unroll
        for (int w = 0; w < 8; w++) a += sm[E_WS + ((chain * 2 + st) * 8 + w) * 32 + c];
        g_epart[chain][st][c][bid] = a;
    }
}

// ---------------- stats finalize ----------------
__global__ void k_fin_edge(const float* __restrict__ gamma, const float* __restrict__ beta) {
    int arr = blockIdx.x >> 5, c = blockIdx.x & 31;
    int tid = threadIdx.x;
    __shared__ double ss[256], sq[256];
    double sa = 0.0, sb = 0.0, qa = 0.0, qb = 0.0;
    const float* ps = &g_epart[arr][0][c][0];
    const float* pz = &g_epart[arr][1][c][0];
    for (int i = tid; i < NBLK; i += 512) {
        sa += ps[i]; qa += pz[i];
        if (i + 256 < NBLK) { sb += ps[i + 256]; qb += pz[i + 256]; }
    }
    ss[tid] = sa + sb; sq[tid] = qa + qb;
    __syncthreads();
    for (int o = 128; o > 0; o >>= 1) {
        if (tid < o) { ss[tid] += ss[tid + o]; sq[tid] += sq[tid + o]; }
        __syncthreads();
    }
    if (tid == 0) {
        double M   = (arr == 0) ? (double)ROWS_C : (double)ER_C;
        double mu  = ss[0] / M;
        double var = sq[0] / M - mu * mu;
        double inv = 1.0 / sqrt(var + BN_EPS);
        g_escale[arr][c] = (float)((double)gamma[c] * inv);
        g_ebias [arr][c] = (float)((double)beta[c] - mu * (double)gamma[c] * inv);
    }
}

__global__ void k_fin_node(const float* __restrict__ gamma, const float* __restrict__ beta) {
    int c = blockIdx.x;
    int tid = threadIdx.x;
    __shared__ double ss[256], sq[256];
    double sa = 0.0, sb = 0.0, qa = 0.0, qb = 0.0;
    const float* ps = &g_npart[0][c][0];
    const float* pz = &g_npart[1][c][0];
    for (int i = tid; i < NBLK; i += 512) {
        sa += ps[i]; qa += pz[i];
        if (i + 256 < NBLK) { sb += ps[i + 256]; qb += pz[i + 256]; }
    }
    ss[tid] = sa + sb; sq[tid] = qa + qb;
    __syncthreads();
    for (int o = 128; o > 0; o >>= 1) {
        if (tid < o) { ss[tid] += ss[tid + o]; sq[tid] += sq[tid + o]; }
        __syncthreads();
    }
    if (tid == 0) {
        double M   = (double)ROWS_C;
        double mu  = ss[0] / M;
        double var = sq[0] / M - mu * mu;
        double inv = 1.0 / sqrt(var + BN_EPS);
        g_nscale[c] = (float)((double)gamma[c] * inv);
        g_nbias [c] = (float)((double)beta[c] - mu * (double)gamma[c] * inv);
    }
}

// ---------------- K2: affine-aggregate cached edges + node MLP + node stats ----------------
__global__ __launch_bounds__(256, 2) void k_node(
    float* __restrict__ dout,
    const float* __restrict__ nW1, const float* __restrict__ nb1,
    const float* __restrict__ nW2, const float* __restrict__ nb2,
    const float* __restrict__ nW3, const float* __restrict__ nb3)
{
    extern __shared__ float sm[];
    const int tid = threadIdx.x, bid = blockIdx.x;
    for (int i = tid; i < 3360; i += 256) {
        float v;
        if      (i < 1024) v = nW1[i];
        else if (i < 1056) v = nb1[i - 1024];
        else if (i < 2080) v = nW2[i - 1056];
        else if (i < 2112) v = nb2[i - 2080];
        else if (i < 3136) v = nW3[i - 2112];
        else if (i < 3168) v = nb3[i - 3136];
        else {
            int k = i - 3168;
            int arr = k / 64, sb = (k >> 5) & 1, c = k & 31;
            v = sb ? g_ebias[arr][c] : g_escale[arr][c];
        }
        sm[i] = v;
    }
    __syncthreads();

    const u64* nW1s = (const u64*)(sm);
    const u64* nB1s = (const u64*)(sm + 1024);
    const u64* nW2s = (const u64*)(sm + 1056);
    const u64* nB2s = (const u64*)(sm + 2080);
    const u64* nW3s = (const u64*)(sm + 2112);
    const u64* nB3s = (const u64*)(sm + 3136);
    const float* s0 = sm + 3168; const float* b0 = sm + 3200;
    const float* s1 = sm + 3232; const float* b1 = sm + 3264;
    const float* s2 = sm + 3296; const float* b2 = sm + 3328;

    int lane = tid & 31, warp = tid >> 5;
    int r_g = lane >> 2, c_g = lane & 3;
    float* Asw = sm + N_A + warp * 2304;
    int r0 = bid * 256 + warp * 32;
    int n0 = bid >> 1;
    int c0 = 8 * c_g;

    float agg[4][8];
    float o[4][8];

#pragma unroll
    for (int rr = 0; rr < 4; rr++) {
        int r = r0 + 4 * r_g + rr;
        int t = r & 511;
        float mf = (t != 0)   ? 1.f : 0.f;
        float mb = (t != 511) ? 1.f : 0.f;

        const float4* ip = reinterpret_cast<const float4*>(dout) + (size_t)r * 8 + c_g * 2;
        float4 va = ip[0], vb = ip[1];
        agg[rr][0] = s0[c0+0]*va.x + b0[c0+0]; agg[rr][1] = s0[c0+1]*va.y + b0[c0+1];
        agg[rr][2] = s0[c0+2]*va.z + b0[c0+2]; agg[rr][3] = s0[c0+3]*va.w + b0[c0+3];
        agg[rr][4] = s0[c0+4]*vb.x + b0[c0+4]; agg[rr][5] = s0[c0+5]*vb.y + b0[c0+5];
        agg[rr][6] = s0[c0+6]*vb.z + b0[c0+6]; agg[rr][7] = s0[c0+7]*vb.w + b0[c0+7];

        {
            long e = (long)r - n0 - 1; if (e < 0) e = 0;
            const float4* fp = reinterpret_cast<const float4*>(g_cf + (size_t)e * 32 + c0);
            float4 fa = fp[0], fb = fp[1];
            agg[rr][0] += mf * (s1[c0+0]*fa.x + b1[c0+0]);
            agg[rr][1] += mf * (s1[c0+1]*fa.y + b1[c0+1]);
            agg[rr][2] += mf * (s1[c0+2]*fa.z + b1[c0+2]);
            agg[rr][3] += mf * (s1[c0+3]*fa.w + b1[c0+3]);
            agg[rr][4] += mf * (s1[c0+4]*fb.x + b1[c0+4]);
            agg[rr][5] += mf * (s1[c0+5]*fb.y + b1[c0+5]);
            agg[rr][6] += mf * (s1[c0+6]*fb.z + b1[c0+6]);
            agg[rr][7] += mf * (s1[c0+7]*fb.w + b1[c0+7]);
        }
        {
            long e = (long)r - n0; if (e > ER_C - 1) e = ER_C - 1;
            const float4* bp = reinterpret_cast<const float4*>(g_cb + (size_t)e * 32 + c0);
            float4 ba = bp[0], bb = bp[1];
            agg[rr][0] += mb * (s2[c0+0]*ba.x + b2[c0+0]);
            agg[rr][1] += mb * (s2[c0+1]*ba.y + b2[c0+1]);
            agg[rr][2] += mb * (s2[c0+2]*ba.z + b2[c0+2]);
            agg[rr][3] += mb * (s2[c0+3]*ba.w + b2[c0+3]);
            agg[rr][4] += mb * (s2[c0+4]*bb.x + b2[c0+4]);
            agg[rr][5] += mb * (s2[c0+5]*bb.y + b2[c0+5]);
            agg[rr][6] += mb * (s2[c0+6]*bb.z + b2[c0+6]);
            agg[rr][7] += mb * (s2[c0+7]*bb.w + b2[c0+7]);
        }
    }

    u64 h[16];
    stage_tile(Asw, r_g, c_g, agg);
    gemm32(Asw, nW1s, nB1s, r_g, c_g, h);
    mlp_tail(Asw, nW2s, nB2s, nW3s, nB3s, r_g, c_g, h);
    unpack_tile(h, o, false);
    store_tile_gmem(dout, r0, r_g, c_g, o);
    {
        float mall[4] = {1.f, 1.f, 1.f, 1.f};
        warp_stats(o, mall, lane, c_g, sm + N_WS + (0 * 8 + warp) * 32, sm + N_WS + (1 * 8 + warp) * 32);
    }

    __syncthreads();
    if (tid < 64) {
        int st = tid >> 5, c = tid & 31;
        float a = 0.f;
#pragma unroll
        for (int w = 0; w < 8; w++) a += sm[N_WS + (st * 8 + w) * 32 + c];
        g_npart[st][c][bid] = a;
    }
}

// ---------------- K3: normalize in place ----------------
__global__ __launch_bounds__(256) void k_final(float* __restrict__ dout) {
    __shared__ float sc[32], bi[32];
    int tid = threadIdx.x;
    if (tid < 32) { sc[tid] = g_nscale[tid]; bi[tid] = g_nbias[tid]; }
    __syncthreads();
    int lane = tid & 31;
    int s = lane & 3;
    int r = (blockIdx.x * 256 + tid) >> 2;
    int c0 = s * 8;
    float4* D4 = reinterpret_cast<float4*>(dout);
    float4 va = D4[(size_t)r * 8 + s * 2];
    float4 vb = D4[(size_t)r * 8 + s * 2 + 1];
    va.x = va.x * sc[c0 + 0] + bi[c0 + 0]; va.y = va.y * sc[c0 + 1] + bi[c0 + 1];
    va.z = va.z * sc[c0 + 2] + bi[c0 + 2]; va.w = va.w * sc[c0 + 3] + bi[c0 + 3];
    vb.x = vb.x * sc[c0 + 4] + bi[c0 + 4]; vb.y = vb.y * sc[c0 + 5] + bi[c0 + 5];
    vb.z = vb.z * sc[c0 + 6] + bi[c0 + 6]; vb.w = vb.w * sc[c0 + 7] + bi[c0 + 7];
    D4[(size_t)r * 8 + s * 2]     = va;
    D4[(size_t)r * 8 + s * 2 + 1] = vb;
}

// ---------------- launch ----------------
extern "C" void kernel_launch(void* const* d_in, const int* in_sizes, int n_in,
                              void* d_out, int out_size)
{
    const float* x    = (const float*)d_in[0];
    const float* eW1  = (const float*)d_in[1];
    const float* eb1  = (const float*)d_in[2];
    const float* eW2  = (const float*)d_in[3];
    const float* eb2  = (const float*)d_in[4];
    const float* eW3  = (const float*)d_in[5];
    const float* eb3  = (const float*)d_in[6];
    const float* eg   = (const float*)d_in[7];
    const float* ebt  = (const float*)d_in[8];
    const float* nW1  = (const float*)d_in[9];
    const float* nb1  = (const float*)d_in[10];
    const float* nW2  = (const float*)d_in[11];
    const float* nb2  = (const float*)d_in[12];
    const float* nW3  = (const float*)d_in[13];
    const float* nb3  = (const float*)d_in[14];
    const float* ng   = (const float*)d_in[15];
    const float* nbt  = (const float*)d_in[16];
    float* out = (float*)d_out;

    cudaFuncSetAttribute(k_edge, cudaFuncAttributeMaxDynamicSharedMemorySize, E_TOT * 4);
    cudaFuncSetAttribute(k_node, cudaFuncAttributeMaxDynamicSharedMemorySize, N_TOT * 4);

    k_edge<<<NBLK, 256, E_TOT * 4>>>(x, out, eW1, eb1, eW2, eb2, eW3, eb3);
    k_fin_edge<<<96, 256>>>(eg, ebt);
    k_node<<<NBLK, 256, N_TOT * 4>>>(out, nW1, nb1, nW2, nb2, nW3, nb3);
    k_fin_node<<<32, 256>>>(ng, nbt);
    k_final<<<ROWS_C * 4 / 256, 256>>>(out);
}

// round 12
// speedup vs baseline: 1.9256x; 1.9256x over previous
#include <cuda_runtime.h>
#include <cstdint>
#include <cstdlib>

// Eager module loading: __device__ globals allocated at context init.
__attribute__((constructor)) static void _force_eager_loading() {
    setenv("CUDA_MODULE_LOADING", "EAGER", 1);
}

#define NN     2048
#define TT     512
#define ROWS_C (NN*TT)        /* 1048576 */
#define ER_C   (NN*(TT-1))    /* 1046528 */
#define BN_EPS 1e-5

// K1: 128 threads = 4 warps x 32 rows, 5 blocks/SM
#define RPB1   128
#define NB1    (ROWS_C/RPB1)  /* 8192 */
// K2: 256 threads = 8 warps x 32 rows, 2 blocks/SM
#define RPB2   256
#define NB2    (ROWS_C/RPB2)  /* 4096 */

typedef unsigned long long u64;

// K1 smem float offsets: weights 0..3712 (incl WC), xT 3712..6016 (4x576),
//                        A 6016..10624 (4x1152), WS 10624..11392
#define E_XT   3712
#define E_A    6016
#define E_WS   10624
#define E_TOT  11392          /* 45568 B -> 5 blocks/SM */
// K2 smem float offsets
#define N_A    3360
#define N_WS   12576
#define N_TOT  13088          /* 52352 B -> 2 blocks/SM */

// ---- device scratch ----
__device__ float g_cf[(size_t)ER_C * 32];   // fwd pre-BN cache (134 MB)
__device__ float g_cb[(size_t)ER_C * 32];   // bwd pre-BN cache (134 MB)
__device__ float g_epart[3][2][32][NB1];
__device__ float g_npart[2][32][NB2];
__device__ float g_escale[3][32], g_ebias[3][32];
__device__ float g_nscale[32],    g_nbias[32];

// ---- packed f32x2 helpers ----
__device__ __forceinline__ u64 pk(float x, float y) {
    u64 d; asm("mov.b64 %0, {%1, %2};" : "=l"(d) : "f"(x), "f"(y)); return d;
}
__device__ __forceinline__ void upk(u64 v, float& lo, float& hi) {
    asm("mov.b64 {%0, %1}, %2;" : "=f"(lo), "=f"(hi) : "l"(v));
}
__device__ __forceinline__ u64 fma2(u64 a, u64 b, u64 c) {
    u64 d; asm("fma.rn.f32x2 %0, %1, %2, %3;" : "=l"(d) : "l"(a), "l"(b), "l"(c)); return d;
}
__device__ __forceinline__ float lrelu(float x) { return fmaxf(x, 0.01f * x); }

// accumulate 4 row-activations against one weight row into the 4x8 tile
__device__ __forceinline__ void accum_row(const u64* __restrict__ wrow, int c_g,
                                          float a0, float a1, float a2, float a3, u64* h) {
    ulonglong2 wA = *reinterpret_cast<const ulonglong2*>(wrow + c_g * 4);
    ulonglong2 wB = *reinterpret_cast<const ulonglong2*>(wrow + c_g * 4 + 2);
    u64 x;
    x = pk(a0, a0); h[0] = fma2(x, wA.x, h[0]); h[1] = fma2(x, wA.y, h[1]);
                    h[2] = fma2(x, wB.x, h[2]); h[3] = fma2(x, wB.y, h[3]);
    x = pk(a1, a1); h[4] = fma2(x, wA.x, h[4]); h[5] = fma2(x, wA.y, h[5]);
                    h[6] = fma2(x, wB.x, h[6]); h[7] = fma2(x, wB.y, h[7]);
    x = pk(a2, a2); h[8] = fma2(x, wA.x, h[8]); h[9] = fma2(x, wA.y, h[9]);
                    h[10] = fma2(x, wB.x, h[10]); h[11] = fma2(x, wB.y, h[11]);
    x = pk(a3, a3); h[12] = fma2(x, wA.x, h[12]); h[13] = fma2(x, wA.y, h[13]);
                    h[14] = fma2(x, wB.x, h[14]); h[15] = fma2(x, wB.y, h[15]);
}

// 32x32 GEMM layer: A staged [k][row] stride 36, lane tile 4 rows x 8 cols
__device__ __forceinline__ void gemm32(const float* __restrict__ As,
                                       const u64* __restrict__ W, const u64* __restrict__ B,
                                       int r_g, int c_g, u64* h) {
#pragma unroll
    for (int cp = 0; cp < 4; cp++) {
        u64 v = B[c_g * 4 + cp];
        h[cp] = v; h[4 + cp] = v; h[8 + cp] = v; h[12 + cp] = v;
    }
#pragma unroll 4
    for (int k = 0; k < 32; k++) {
        float4 t = *reinterpret_cast<const float4*>(As + k * 36 + 4 * r_g);
        accum_row(W + k * 16, c_g, t.x, t.y, t.z, t.w, h);
    }
}

__device__ __forceinline__ void unpack_tile(const u64* h, float o[4][8], bool relu) {
#pragma unroll
    for (int r = 0; r < 4; r++)
#pragma unroll
        for (int cp = 0; cp < 4; cp++) {
            float lo, hi; upk(h[r * 4 + cp], lo, hi);
            o[r][2 * cp]     = relu ? lrelu(lo) : lo;
            o[r][2 * cp + 1] = relu ? lrelu(hi) : hi;
        }
}

// store lane tile transposed into A buffer (A[col][row], stride 36)
__device__ __forceinline__ void stage_tile(float* As, int r_g, int c_g, const float o[4][8]) {
    __syncwarp();
#pragma unroll
    for (int cc = 0; cc < 8; cc++) {
        *reinterpret_cast<float4*>(As + (8 * c_g + cc) * 36 + 4 * r_g) =
            make_float4(o[0][cc], o[1][cc], o[2][cc], o[3][cc]);
    }
    __syncwarp();
}

// L2 + L3 of a 3-layer MLP (h already holds L1 pre-act)
__device__ __forceinline__ void mlp_tail(float* As,
                                         const u64* W2, const u64* B2,
                                         const u64* W3, const u64* B3,
                                         int r_g, int c_g, u64* h) {
    float o[4][8];
    unpack_tile(h, o, true);
    stage_tile(As, r_g, c_g, o);
    gemm32(As, W2, B2, r_g, c_g, h);
    unpack_tile(h, o, true);
    stage_tile(As, r_g, c_g, o);
    gemm32(As, W3, B3, r_g, c_g, h);
}

// edge layer-1: two 16-wide segments from xT (stride 36) + dir column
template<bool PA, bool QA>
__device__ __forceinline__ void edge_L1(const float* __restrict__ xTw, int po, int qo, float dir,
                                        const u64* __restrict__ W1, const u64* __restrict__ B1,
                                        int r_g, int c_g, u64* h) {
    u64 dp = pk(dir, dir);
#pragma unroll
    for (int cp = 0; cp < 4; cp++) {
        u64 v = fma2(dp, W1[32 * 16 + c_g * 4 + cp], B1[c_g * 4 + cp]);
        h[cp] = v; h[4 + cp] = v; h[8 + cp] = v; h[12 + cp] = v;
    }
#pragma unroll 4
    for (int k = 0; k < 16; k++) {
        const float* p = xTw + k * 36 + 4 * r_g + po;
        float a0, a1, a2, a3;
        if (PA) { float4 t = *reinterpret_cast<const float4*>(p); a0 = t.x; a1 = t.y; a2 = t.z; a3 = t.w; }
        else    { a0 = p[0]; a1 = p[1]; a2 = p[2]; a3 = p[3]; }
        accum_row(W1 + k * 16, c_g, a0, a1, a2, a3, h);
    }
#pragma unroll 4
    for (int k = 0; k < 16; k++) {
        const float* p = xTw + k * 36 + 4 * r_g + qo;
        float a0, a1, a2, a3;
        if (QA) { float4 t = *reinterpret_cast<const float4*>(p); a0 = t.x; a1 = t.y; a2 = t.z; a3 = t.w; }
        else    { a0 = p[0]; a1 = p[1]; a2 = p[2]; a3 = p[3]; }
        accum_row(W1 + (16 + k) * 16, c_g, a0, a1, a2, a3, h);
    }
}

// inplace edge layer-1 with combined weights (p==q): 16 k-steps
__device__ __forceinline__ void edge_L1_inplace(const float* __restrict__ xTw,
                                                const u64* __restrict__ WC, const u64* __restrict__ B1,
                                                int r_g, int c_g, u64* h) {
#pragma unroll
    for (int cp = 0; cp < 4; cp++) {
        u64 v = B1[c_g * 4 + cp];
        h[cp] = v; h[4 + cp] = v; h[8 + cp] = v; h[12 + cp] = v;
    }
#pragma unroll 4
    for (int k = 0; k < 16; k++) {
        float4 t = *reinterpret_cast<const float4*>(xTw + k * 36 + 4 * r_g);
        accum_row(WC + k * 16, c_g, t.x, t.y, t.z, t.w, h);
    }
}

// per-warp masked per-channel sum/sumsq -> ws[warp][c]
__device__ __forceinline__ void warp_stats(const float o[4][8], const float m[4],
                                           int lane, int c_g, float* wsS, float* wsQ) {
    float s[8], q[8];
#pragma unroll
    for (int cc = 0; cc < 8; cc++) { s[cc] = 0.f; q[cc] = 0.f; }
#pragma unroll
    for (int r = 0; r < 4; r++)
#pragma unroll
        for (int cc = 0; cc < 8; cc++) {
            float v = o[r][cc] * m[r];
            s[cc] += v; q[cc] += v * v;
        }
#pragma unroll
    for (int msk = 4; msk <= 16; msk <<= 1)
#pragma unroll
        for (int cc = 0; cc < 8; cc++) {
            s[cc] += __shfl_xor_sync(0xffffffffu, s[cc], msk);
            q[cc] += __shfl_xor_sync(0xffffffffu, q[cc], msk);
        }
    if (lane < 4) {
#pragma unroll
        for (int cc = 0; cc < 8; cc++) { wsS[8 * c_g + cc] = s[cc]; wsQ[8 * c_g + cc] = q[cc]; }
    }
}

__device__ __forceinline__ void store_tile_gmem(float* __restrict__ dout, int r0,
                                                int r_g, int c_g, const float o[4][8]) {
#pragma unroll
    for (int rr = 0; rr < 4; rr++) {
        float4* p = reinterpret_cast<float4*>(dout) + (size_t)(r0 + 4 * r_g + rr) * 8 + c_g * 2;
        p[0] = make_float4(o[rr][0], o[rr][1], o[rr][2], o[rr][3]);
        p[1] = make_float4(o[rr][4], o[rr][5], o[rr][6], o[rr][7]);
    }
}

// store lane tile to edge cache [e][32], e = r - n; skip rows with t==511
__device__ __forceinline__ void store_tile_cache(float* __restrict__ dst, int r0,
                                                 int r_g, int c_g, const float o[4][8]) {
#pragma unroll
    for (int rr = 0; rr < 4; rr++) {
        int r = r0 + 4 * r_g + rr;
        if ((r & 511) != 511) {
            int e = r - (r >> 9);
            float4* p = reinterpret_cast<float4*>(dst + (size_t)e * 32 + 8 * c_g);
            p[0] = make_float4(o[rr][0], o[rr][1], o[rr][2], o[rr][3]);
            p[1] = make_float4(o[rr][4], o[rr][5], o[rr][6], o[rr][7]);
        }
    }
}

// ---------------- K1: 3 edge chains; inplace -> dout, fwd/bwd -> caches; stats ----------------
__global__ __launch_bounds__(128, 5) void k_edge(
    const float* __restrict__ x, float* __restrict__ dout,
    const float* __restrict__ eW1, const float* __restrict__ eb1,
    const float* __restrict__ eW2, const float* __restrict__ eb2,
    const float* __restrict__ eW3, const float* __restrict__ eb3)
{
    extern __shared__ float sm[];
    const int tid = threadIdx.x, bid = blockIdx.x;
    for (int i = tid; i < 3200; i += 128) {
        float v;
        if      (i < 1056) v = eW1[i];
        else if (i < 1088) v = eb1[i - 1056];
        else if (i < 2112) v = eW2[i - 1088];
        else if (i < 2144) v = eb2[i - 2112];
        else if (i < 3168) v = eW3[i - 2144];
        else               v = eb3[i - 3168];
        sm[i] = v;
    }
    for (int i = tid; i < 512; i += 128) {
        int k = i >> 5, j = i & 31;
        sm[3200 + i] = eW1[k * 32 + j] + eW1[(k + 16) * 32 + j];
    }
    for (int idx = tid; idx < 4 * 528; idx += 128) {
        int w = idx / 528, rem = idx - w * 528;
        int k = rem & 15, i = rem >> 4;
        int row = bid * RPB1 + w * 32 + i;
        if (row > ROWS_C - 1) row = ROWS_C - 1;
        sm[E_XT + w * 576 + k * 36 + i] = x[(size_t)row * 16 + k];
    }
    __syncthreads();

    const u64* W1 = (const u64*)(sm);
    const u64* B1 = (const u64*)(sm + 1056);
    const u64* W2 = (const u64*)(sm + 1088);
    const u64* B2 = (const u64*)(sm + 2112);
    const u64* W3 = (const u64*)(sm + 2144);
    const u64* B3 = (const u64*)(sm + 3168);
    const u64* WC = (const u64*)(sm + 3200);

    int lane = tid & 31, warp = tid >> 5;
    int r_g = lane >> 2, c_g = lane & 3;
    const float* xTw = sm + E_XT + warp * 576;
    float* Asw = sm + E_A + warp * 1152;
    int r0 = bid * RPB1 + warp * 32;

    float mk[4], mall[4];
#pragma unroll
    for (int rr = 0; rr < 4; rr++) {
        mall[rr] = 1.f;
        mk[rr] = (((r0 + 4 * r_g + rr) & 511) != 511) ? 1.f : 0.f;
    }

    u64 h[16];
    float o[4][8];

    // inplace: [x_t, x_t, 0]
    edge_L1_inplace(xTw, WC, B1, r_g, c_g, h);
    mlp_tail(Asw, W2, B2, W3, B3, r_g, c_g, h);
    unpack_tile(h, o, false);
    store_tile_gmem(dout, r0, r_g, c_g, o);
    warp_stats(o, mall, lane, c_g, sm + E_WS + (0 * 4 + warp) * 32, sm + E_WS + (1 * 4 + warp) * 32);

    // fwd edge (t, t+1): [x_{t+1}, x_t, +1] -> p off 1 (scalar), q off 0 (vec)
    edge_L1<false, true>(xTw, 1, 0, 1.f, W1, B1, r_g, c_g, h);
    mlp_tail(Asw, W2, B2, W3, B3, r_g, c_g, h);
    unpack_tile(h, o, false);
    store_tile_cache(g_cf, r0, r_g, c_g, o);
    warp_stats(o, mk, lane, c_g, sm + E_WS + (2 * 4 + warp) * 32, sm + E_WS + (3 * 4 + warp) * 32);

    // bwd edge (t, t+1): [x_t, x_{t+1}, -1] -> p off 0 (vec), q off 1 (scalar)
    edge_L1<true, false>(xTw, 0, 1, -1.f, W1, B1, r_g, c_g, h);
    mlp_tail(Asw, W2, B2, W3, B3, r_g, c_g, h);
    unpack_tile(h, o, false);
    store_tile_cache(g_cb, r0, r_g, c_g, o);
    warp_stats(o, mk, lane, c_g, sm + E_WS + (4 * 4 + warp) * 32, sm + E_WS + (5 * 4 + warp) * 32);

    __syncthreads();
    for (int idx = tid; idx < 192; idx += 128) {
        int chain = idx / 64, st = (idx >> 5) & 1, c = idx & 31;
        float a = 0.f;
#pragma unroll
        for (int w = 0; w < 4; w++) a += sm[E_WS + ((chain * 2 + st) * 4 + w) * 32 + c];
        g_epart[chain][st][c][bid] = a;
    }
}

// ---------------- stats finalize ----------------
__global__ void k_fin_edge(const float* __restrict__ gamma, const float* __restrict__ beta) {
    int arr = blockIdx.x >> 5, c = blockIdx.x & 31;
    int tid = threadIdx.x;
    __shared__ double ss[256], sq[256];
    double sa = 0.0, sb = 0.0, qa = 0.0, qb = 0.0;
    const float* ps = &g_epart[arr][0][c][0];
    const float* pz = &g_epart[arr][1][c][0];
    for (int i = tid; i < NB1; i += 512) {
        sa += ps[i]; qa += pz[i];
        if (i + 256 < NB1) { sb += ps[i + 256]; qb += pz[i + 256]; }
    }
    ss[tid] = sa + sb; sq[tid] = qa + qb;
    __syncthreads();
    for (int o = 128; o > 0; o >>= 1) {
        if (tid < o) { ss[tid] += ss[tid + o]; sq[tid] += sq[tid + o]; }
        __syncthreads();
    }
    if (tid == 0) {
        double M   = (arr == 0) ? (double)ROWS_C : (double)ER_C;
        double mu  = ss[0] / M;
        double var = sq[0] / M - mu * mu;
        double inv = 1.0 / sqrt(var + BN_EPS);
        g_escale[arr][c] = (float)((double)gamma[c] * inv);
        g_ebias [arr][c] = (float)((double)beta[c] - mu * (double)gamma[c] * inv);
    }
}

__global__ void k_fin_node(const float* __restrict__ gamma, const float* __restrict__ beta) {
    int c = blockIdx.x;
    int tid = threadIdx.x;
    __shared__ double ss[256], sq[256];
    double sa = 0.0, sb = 0.0, qa = 0.0, qb = 0.0;
    const float* ps = &g_npart[0][c][0];
    const float* pz = &g_npart[1][c][0];
    for (int i = tid; i < NB2; i += 512) {
        sa += ps[i]; qa += pz[i];
        if (i + 256 < NB2) { sb += ps[i + 256]; qb += pz[i + 256]; }
    }
    ss[tid] = sa + sb; sq[tid] = qa + qb;
    __syncthreads();
    for (int o = 128; o > 0; o >>= 1) {
        if (tid < o) { ss[tid] += ss[tid + o]; sq[tid] += sq[tid + o]; }
        __syncthreads();
    }
    if (tid == 0) {
        double M   = (double)ROWS_C;
        double mu  = ss[0] / M;
        double var = sq[0] / M - mu * mu;
        double inv = 1.0 / sqrt(var + BN_EPS);
        g_nscale[c] = (float)((double)gamma[c] * inv);
        g_nbias [c] = (float)((double)beta[c] - mu * (double)gamma[c] * inv);
    }
}

// ---------------- K2: affine-aggregate cached edges + node MLP + node stats ----------------
__global__ __launch_bounds__(256, 2) void k_node(
    float* __restrict__ dout,
    const float* __restrict__ nW1, const float* __restrict__ nb1,
    const float* __restrict__ nW2, const float* __restrict__ nb2,
    const float* __restrict__ nW3, const float* __restrict__ nb3)
{
    extern __shared__ float sm[];
    const int tid = threadIdx.x, bid = blockIdx.x;
    for (int i = tid; i < 3360; i += 256) {
        float v;
        if      (i < 1024) v = nW1[i];
        else if (i < 1056) v = nb1[i - 1024];
        else if (i < 2080) v = nW2[i - 1056];
        else if (i < 2112) v = nb2[i - 2080];
        else if (i < 3136) v = nW3[i - 2112];
        else if (i < 3168) v = nb3[i - 3136];
        else {
            int k = i - 3168;
            int arr = k / 64, sb = (k >> 5) & 1, c = k & 31;
            v = sb ? g_ebias[arr][c] : g_escale[arr][c];
        }
        sm[i] = v;
    }
    __syncthreads();

    const u64* nW1s = (const u64*)(sm);
    const u64* nB1s = (const u64*)(sm + 1024);
    const u64* nW2s = (const u64*)(sm + 1056);
    const u64* nB2s = (const u64*)(sm + 2080);
    const u64* nW3s = (const u64*)(sm + 2112);
    const u64* nB3s = (const u64*)(sm + 3136);
    const float* s0 = sm + 3168; const float* b0 = sm + 3200;
    const float* s1 = sm + 3232; const float* b1 = sm + 3264;
    const float* s2 = sm + 3296; const float* b2 = sm + 3328;

    int lane = tid & 31, warp = tid >> 5;
    int r_g = lane >> 2, c_g = lane & 3;
    float* Asw = sm + N_A + warp * 1152;
    int r0 = bid * 256 + warp * 32;
    int n0 = bid >> 1;
    int c0 = 8 * c_g;

    float agg[4][8];
    float o[4][8];

#pragma unroll
    for (int rr = 0; rr < 4; rr++) {
        int r = r0 + 4 * r_g + rr;
        int t = r & 511;
        float mf = (t != 0)   ? 1.f : 0.f;
        float mb = (t != 511) ? 1.f : 0.f;

        const float4* ip = reinterpret_cast<const float4*>(dout) + (size_t)r * 8 + c_g * 2;
        float4 va = ip[0], vb = ip[1];
        agg[rr][0] = s0[c0+0]*va.x + b0[c0+0]; agg[rr][1] = s0[c0+1]*va.y + b0[c0+1];
        agg[rr][2] = s0[c0+2]*va.z + b0[c0+2]; agg[rr][3] = s0[c0+3]*va.w + b0[c0+3];
        agg[rr][4] = s0[c0+4]*vb.x + b0[c0+4]; agg[rr][5] = s0[c0+5]*vb.y + b0[c0+5];
        agg[rr][6] = s0[c0+6]*vb.z + b0[c0+6]; agg[rr][7] = s0[c0+7]*vb.w + b0[c0+7];

        {
            long e = (long)r - n0 - 1; if (e < 0) e = 0;
            const float4* fp = reinterpret_cast<const float4*>(g_cf + (size_t)e * 32 + c0);
            float4 fa = fp[0], fb = fp[1];
            agg[rr][0] += mf * (s1[c0+0]*fa.x + b1[c0+0]);
            agg[rr][1] += mf * (s1[c0+1]*fa.y + b1[c0+1]);
            agg[rr][2] += mf * (s1[c0+2]*fa.z + b1[c0+2]);
            agg[rr][3] += mf * (s1[c0+3]*fa.w + b1[c0+3]);
            agg[rr][4] += mf * (s1[c0+4]*fb.x + b1[c0+4]);
            agg[rr][5] += mf * (s1[c0+5]*fb.y + b1[c0+5]);
            agg[rr][6] += mf * (s1[c0+6]*fb.z + b1[c0+6]);
            agg[rr][7] += mf * (s1[c0+7]*fb.w + b1[c0+7]);
        }
        {
            long e = (long)r - n0; if (e > ER_C - 1) e = ER_C - 1;
            const float4* bp = reinterpret_cast<const float4*>(g_cb + (size_t)e * 32 + c0);
            float4 ba = bp[0], bb = bp[1];
            agg[rr][0] += mb * (s2[c0+0]*ba.x + b2[c0+0]);
            agg[rr][1] += mb * (s2[c0+1]*ba.y + b2[c0+1]);
            agg[rr][2] += mb * (s2[c0+2]*ba.z + b2[c0+2]);
            agg[rr][3] += mb * (s2[c0+3]*ba.w + b2[c0+3]);
            agg[rr][4] += mb * (s2[c0+4]*bb.x + b2[c0+4]);
            agg[rr][5] += mb * (s2[c0+5]*bb.y + b2[c0+5]);
            agg[rr][6] += mb * (s2[c0+6]*bb.z + b2[c0+6]);
            agg[rr][7] += mb * (s2[c0+7]*bb.w + b2[c0+7]);
        }
    }

    u64 h[16];
    stage_tile(Asw, r_g, c_g, agg);
    gemm32(Asw, nW1s, nB1s, r_g, c_g, h);
    mlp_tail(Asw, nW2s, nB2s, nW3s, nB3s, r_g, c_g, h);
    unpack_tile(h, o, false);
    store_tile_gmem(dout, r0, r_g, c_g, o);
    {
        float mall[4] = {1.f, 1.f, 1.f, 1.f};
        warp_stats(o, mall, lane, c_g, sm + N_WS + (0 * 8 + warp) * 32, sm + N_WS + (1 * 8 + warp) * 32);
    }

    __syncthreads();
    if (tid < 64) {
        int st = tid >> 5, c = tid & 31;
        float a = 0.f;
#pragma unroll
        for (int w = 0; w < 8; w++) a += sm[N_WS + (st * 8 + w) * 32 + c];
        g_npart[st][c][bid] = a;
    }
}

// ---------------- K3: normalize in place ----------------
__global__ __launch_bounds__(256) void k_final(float* __restrict__ dout) {
    __shared__ float sc[32], bi[32];
    int tid = threadIdx.x;
    if (tid < 32) { sc[tid] = g_nscale[tid]; bi[tid] = g_nbias[tid]; }
    __syncthreads();
    int lane = tid & 31;
    int s = lane & 3;
    int r = (blockIdx.x * 256 + tid) >> 2;
    int c0 = s * 8;
    float4* D4 = reinterpret_cast<float4*>(dout);
    float4 va = D4[(size_t)r * 8 + s * 2];
    float4 vb = D4[(size_t)r * 8 + s * 2 + 1];
    va.x = va.x * sc[c0 + 0] + bi[c0 + 0]; va.y = va.y * sc[c0 + 1] + bi[c0 + 1];
    va.z = va.z * sc[c0 + 2] + bi[c0 + 2]; va.w = va.w * sc[c0 + 3] + bi[c0 + 3];
    vb.x = vb.x * sc[c0 + 4] + bi[c0 + 4]; vb.y = vb.y * sc[c0 + 5] + bi[c0 + 5];
    vb.z = vb.z * sc[c0 + 6] + bi[c0 + 6]; vb.w = vb.w * sc[c0 + 7] + bi[c0 + 7];
    D4[(size_t)r * 8 + s * 2]     = va;
    D4[(size_t)r * 8 + s * 2 + 1] = vb;
}

// ---------------- launch ----------------
extern "C" void kernel_launch(void* const* d_in, const int* in_sizes, int n_in,
                              void* d_out, int out_size)
{
    const float* x    = (const float*)d_in[0];
    const float* eW1  = (const float*)d_in[1];
    const float* eb1  = (const float*)d_in[2];
    const float* eW2  = (const float*)d_in[3];
    const float* eb2  = (const float*)d_in[4];
    const float* eW3  = (const float*)d_in[5];
    const float* eb3  = (const float*)d_in[6];
    const float* eg   = (const float*)d_in[7];
    const float* ebt  = (const float*)d_in[8];
    const float* nW1  = (const float*)d_in[9];
    const float* nb1  = (const float*)d_in[10];
    const float* nW2  = (const float*)d_in[11];
    const float* nb2  = (const float*)d_in[12];
    const float* nW3  = (const float*)d_in[13];
    const float* nb3  = (const float*)d_in[14];
    const float* ng   = (const float*)d_in[15];
    const float* nbt  = (const float*)d_in[16];
    float* out = (float*)d_out;

    cudaFuncSetAttribute(k_edge, cudaFuncAttributeMaxDynamicSharedMemorySize, E_TOT * 4);
    cudaFuncSetAttribute(k_node, cudaFuncAttributeMaxDynamicSharedMemorySize, N_TOT * 4);

    k_edge<<<NB1, RPB1, E_TOT * 4>>>(x, out, eW1, eb1, eW2, eb2, eW3, eb3);
    k_fin_edge<<<96, 256>>>(eg, ebt);
    k_node<<<NB2, 256, N_TOT * 4>>>(out, nW1, nb1, nW2, nb2, nW3, nb3);
    k_fin_node<<<32, 256>>>(ng, nbt);
    k_final<<<ROWS_C * 4 / 256, 256>>>(out);
}

// round 14
// speedup vs baseline: 2.2504x; 1.1687x over previous
#include <cuda_runtime.h>
#include <cuda_bf16.h>
#include <cstdint>
#include <cstdlib>

// Eager module loading: __device__ globals allocated at context init.
__attribute__((constructor)) static void _force_eager_loading() {
    setenv("CUDA_MODULE_LOADING", "EAGER", 1);
}

#define NN     2048
#define TT     512
#define ROWS_C (NN*TT)        /* 1048576 */
#define ER_C   (NN*(TT-1))    /* 1046528 */
#define BN_EPS 1e-5

#define NB1    8192           /* K1 blocks, 128 rows each */
#define RPB2   256
#define NB2    (ROWS_C/RPB2)  /* 4096 */

typedef unsigned long long u64;

// ---- K1 smem float offsets ----
// WF (u32 frag tables) 0..3584, BIAS 3584..3744, XS 3744..5808 (129x16),
// BOUNCE 5808..10416 (4 warps x 32x36), WS 10416..11184
#define WF_U   0
#define BIAS_F 3584
#define XS_F   3744
#define BO_F   5808
#define WS_F   10416
#define K1_TOT 11184          /* 44736 B */
// frag table blocks (256 u32 each): WC hi/lo, W1 hi(2kc)/lo(2kc), W2, W3
#define BLK_WC_H 0
#define BLK_WC_L 1
#define BLK_W1_H 2
#define BLK_W1_L 4
#define BLK_W2_H 6
#define BLK_W2_L 8
#define BLK_W3_H 10
#define BLK_W3_L 12

// ---- K2 smem float offsets (FFMA path, R12) ----
#define N_A    3360
#define N_WS   12576
#define N_TOT  13088

// ---- device scratch ----
__device__ float g_cf[(size_t)ER_C * 32];
__device__ float g_cb[(size_t)ER_C * 32];
__device__ float g_epart[3][2][32][NB1];
__device__ float g_npart[2][32][NB2];
__device__ float g_escale[3][32], g_ebias[3][32];
__device__ float g_nscale[32],    g_nbias[32];

__device__ __forceinline__ float lrelu(float x) { return fmaxf(x, 0.01f * x); }

// ---- bf16 split helpers ----
__device__ __forceinline__ void bsplit(float v, unsigned short& h, unsigned short& l) {
    __nv_bfloat16 hb = __float2bfloat16_rn(v);
    float rest = v - __bfloat162float(hb);
    __nv_bfloat16 lb = __float2bfloat16_rn(rest);
    h = __bfloat16_as_ushort(hb);
    l = __bfloat16_as_ushort(lb);
}
__device__ __forceinline__ void split_pack2(float v0, float v1, uint32_t& hp, uint32_t& lp) {
    unsigned short h0, l0, h1, l1;
    bsplit(v0, h0, l0); bsplit(v1, h1, l1);
    hp = (uint32_t)h0 | ((uint32_t)h1 << 16);
    lp = (uint32_t)l0 | ((uint32_t)l1 << 16);
}

// ---- HMMA m16n8k16 bf16 (baseline ISA, sm_80+) ----
__device__ __forceinline__ void mma4(float* c, const uint32_t* a, uint32_t b0, uint32_t b1) {
    asm volatile(
        "mma.sync.aligned.m16n8k16.row.col.f32.bf16.bf16.f32 "
        "{%0,%1,%2,%3}, {%4,%5,%6,%7}, {%8,%9}, {%0,%1,%2,%3};"
        : "+f"(c[0]), "+f"(c[1]), "+f"(c[2]), "+f"(c[3])
        : "r"(a[0]), "r"(a[1]), "r"(a[2]), "r"(a[3]), "r"(b0), "r"(b1));
}

// one K16-chunk of a 32xN32 layer; 3-product bf16 split
__device__ __forceinline__ void gemm_kc(const uint32_t* __restrict__ WFu,
        int blkH, int blkL, int kc,
        const uint32_t* aH, const uint32_t* aL, int lane, float* C)
{
    const uint4* ph = (const uint4*)(WFu + (blkH + kc) * 256 + lane * 4);
    const uint4* pl = (const uint4*)(WFu + (blkL + kc) * 256 + lane * 4);
    uint4 H0 = ph[0], H1 = ph[32];
    uint4 L0 = pl[0], L1 = pl[32];
#pragma unroll
    for (int mt = 0; mt < 2; mt++) {
        const uint32_t* ah = aH + mt * 4;
        const uint32_t* al = aL + mt * 4;
        float* c = C + mt * 16;
        mma4(c + 0,  ah, H0.x, H0.y); mma4(c + 0,  al, H0.x, H0.y); mma4(c + 0,  ah, L0.x, L0.y);
        mma4(c + 4,  ah, H0.z, H0.w); mma4(c + 4,  al, H0.z, H0.w); mma4(c + 4,  ah, L0.z, L0.w);
        mma4(c + 8,  ah, H1.x, H1.y); mma4(c + 8,  al, H1.x, H1.y); mma4(c + 8,  ah, L1.x, L1.y);
        mma4(c + 12, ah, H1.z, H1.w); mma4(c + 12, al, H1.z, H1.w); mma4(c + 12, ah, L1.z, L1.w);
    }
}

__device__ __forceinline__ void init_C(const float* bias, int t, float* C) {
#pragma unroll
    for (int nt = 0; nt < 4; nt++) {
        float b0 = bias[8 * nt + 2 * t];
        float b1 = bias[8 * nt + 2 * t + 1];
#pragma unroll
        for (int mt = 0; mt < 2; mt++) {
            C[mt*16 + nt*4 + 0] = b0; C[mt*16 + nt*4 + 1] = b1;
            C[mt*16 + nt*4 + 2] = b0; C[mt*16 + nt*4 + 3] = b1;
        }
    }
}

// relu + split C -> next-layer A frags (thread-local repack; no shuffles)
__device__ __forceinline__ void epi_split(const float* C, uint32_t* AH, uint32_t* AL) {
#pragma unroll
    for (int mt = 0; mt < 2; mt++)
#pragma unroll
        for (int kc = 0; kc < 2; kc++) {
            int j0 = 2 * kc, j1 = 2 * kc + 1;
            float v0 = lrelu(C[mt*16 + j0*4 + 0]), v1 = lrelu(C[mt*16 + j0*4 + 1]);
            float v2 = lrelu(C[mt*16 + j0*4 + 2]), v3 = lrelu(C[mt*16 + j0*4 + 3]);
            float u0 = lrelu(C[mt*16 + j1*4 + 0]), u1 = lrelu(C[mt*16 + j1*4 + 1]);
            float u2 = lrelu(C[mt*16 + j1*4 + 2]), u3 = lrelu(C[mt*16 + j1*4 + 3]);
            split_pack2(v0, v1, AH[kc*8 + mt*4 + 0], AL[kc*8 + mt*4 + 0]);
            split_pack2(v2, v3, AH[kc*8 + mt*4 + 1], AL[kc*8 + mt*4 + 1]);
            split_pack2(u0, u1, AH[kc*8 + mt*4 + 2], AL[kc*8 + mt*4 + 2]);
            split_pack2(u2, u3, AH[kc*8 + mt*4 + 3], AL[kc*8 + mt*4 + 3]);
        }
}

// ---------------- K1: tensor-core (HMMA) edge chains ----------------
__global__ __launch_bounds__(128, 3) void k_edge_tc(
    const float* __restrict__ x, float* __restrict__ dout,
    const float* __restrict__ eW1, const float* __restrict__ eb1,
    const float* __restrict__ eW2, const float* __restrict__ eb2,
    const float* __restrict__ eW3, const float* __restrict__ eb3)
{
    extern __shared__ float smf[];
    uint32_t* WFu = (uint32_t*)smf;
    const int tid = threadIdx.x, bid = blockIdx.x;
    const int lane = tid & 31, warp = tid >> 5;
    const int g = lane >> 2, t = lane & 3;
    const int r0 = bid * 128;

    // bias variants
    if (tid < 32) {
        float b1v = eb1[tid], wd = eW1[1024 + tid];
        smf[BIAS_F + tid]       = b1v;
        smf[BIAS_F + 32 + tid]  = b1v + wd;
        smf[BIAS_F + 64 + tid]  = b1v - wd;
        smf[BIAS_F + 96 + tid]  = eb2[tid];
        smf[BIAS_F + 128 + tid] = eb3[tid];
    }
    // x staging: 129 rows x 16 (row r0+128 clamped)
    for (int idx = tid; idx < 129 * 16; idx += 128) {
        int row = r0 + (idx >> 4);
        if (row > ROWS_C - 1) row = ROWS_C - 1;
        smf[XS_F + idx] = x[(size_t)row * 16 + (idx & 15)];
    }
    // weight B-fragment tables
    for (int idx = tid; idx < 3584; idx += 128) {
        int blk = idx >> 8;
        int rem = idx & 255;
        int j4 = rem >> 7;
        int ln = (rem >> 2) & 31;
        int q  = rem & 3;
        int gg = ln >> 2, tt = ln & 3;
        int nt = 2 * j4 + (q >> 1);
        int rg = q & 1;
        int n  = 8 * nt + gg;
        int half, kc, which;
        if (blk < 2)       { which = 0; half = blk;          kc = 0; }
        else if (blk < 6)  { which = 1; half = (blk - 2) >> 1;  kc = (blk - 2) & 1; }
        else if (blk < 10) { which = 2; half = (blk - 6) >> 1;  kc = (blk - 6) & 1; }
        else               { which = 3; half = (blk - 10) >> 1; kc = (blk - 10) & 1; }
        int k0 = 16 * kc + 2 * tt + 8 * rg;
        float w0, w1;
        if (which == 0)      { w0 = eW1[k0*32+n] + eW1[(k0+16)*32+n];
                               w1 = eW1[(k0+1)*32+n] + eW1[(k0+17)*32+n]; }
        else if (which == 1) { w0 = eW1[k0*32+n]; w1 = eW1[(k0+1)*32+n]; }
        else if (which == 2) { w0 = eW2[k0*32+n]; w1 = eW2[(k0+1)*32+n]; }
        else                 { w0 = eW3[k0*32+n]; w1 = eW3[(k0+1)*32+n]; }
        unsigned short h0, l0, h1, l1;
        bsplit(w0, h0, l0); bsplit(w1, h1, l1);
        WFu[blk * 256 + j4 * 128 + ln * 4 + q] =
            (half == 0) ? ((uint32_t)h0 | ((uint32_t)h1 << 16))
                        : ((uint32_t)l0 | ((uint32_t)l1 << 16));
    }
    __syncthreads();

    const int wrow = warp * 32;
    float* bw = smf + BO_F + warp * 1152;

    // x A-frags (Xc = x_t rows, Xn = x_{t+1})
    uint32_t XcH[8], XcL[8], XnH[8], XnL[8];
#pragma unroll
    for (int mt = 0; mt < 2; mt++)
#pragma unroll
        for (int rr = 0; rr < 2; rr++) {
            int rl = wrow + mt * 16 + rr * 8 + g;
            float2 vA = *(const float2*)(smf + XS_F + rl * 16 + 2 * t);
            float2 vB = *(const float2*)(smf + XS_F + rl * 16 + 2 * t + 8);
            split_pack2(vA.x, vA.y, XcH[mt*4 + rr],     XcL[mt*4 + rr]);
            split_pack2(vB.x, vB.y, XcH[mt*4 + 2 + rr], XcL[mt*4 + 2 + rr]);
            float2 nA = *(const float2*)(smf + XS_F + (rl + 1) * 16 + 2 * t);
            float2 nB = *(const float2*)(smf + XS_F + (rl + 1) * 16 + 2 * t + 8);
            split_pack2(nA.x, nA.y, XnH[mt*4 + rr],     XnL[mt*4 + rr]);
            split_pack2(nB.x, nB.y, XnH[mt*4 + 2 + rr], XnL[mt*4 + 2 + rr]);
        }

    uint32_t A2H[16], A2L[16];
    float C[32];

#pragma unroll
    for (int ch = 0; ch < 3; ch++) {
        // ---- L1 ----
        init_C(smf + BIAS_F + ch * 32, t, C);
        if (ch == 0) {
            gemm_kc(WFu, BLK_WC_H, BLK_WC_L, 0, XcH, XcL, lane, C);
        } else if (ch == 1) {   // fwd: [x_{t+1} | x_t]
            gemm_kc(WFu, BLK_W1_H, BLK_W1_L, 0, XnH, XnL, lane, C);
            gemm_kc(WFu, BLK_W1_H, BLK_W1_L, 1, XcH, XcL, lane, C);
        } else {                // bwd: [x_t | x_{t+1}]
            gemm_kc(WFu, BLK_W1_H, BLK_W1_L, 0, XcH, XcL, lane, C);
            gemm_kc(WFu, BLK_W1_H, BLK_W1_L, 1, XnH, XnL, lane, C);
        }
        // ---- L2 ----
        epi_split(C, A2H, A2L);
        init_C(smf + BIAS_F + 96, t, C);
        gemm_kc(WFu, BLK_W2_H, BLK_W2_L, 0, A2H,     A2L,     lane, C);
        gemm_kc(WFu, BLK_W2_H, BLK_W2_L, 1, A2H + 8, A2L + 8, lane, C);
        // ---- L3 ----
        epi_split(C, A2H, A2L);
        init_C(smf + BIAS_F + 128, t, C);
        gemm_kc(WFu, BLK_W3_H, BLK_W3_L, 0, A2H,     A2L,     lane, C);
        gemm_kc(WFu, BLK_W3_H, BLK_W3_L, 1, A2H + 8, A2L + 8, lane, C);

        // ---- bounce + stats + stores (per-warp, no block sync) ----
        __syncwarp();
#pragma unroll
        for (int mt = 0; mt < 2; mt++)
#pragma unroll
            for (int nt = 0; nt < 4; nt++) {
                int ra = mt * 16 + g, rb = ra + 8;
                *(float2*)(bw + ra * 36 + 8 * nt + 2 * t) =
                    make_float2(C[mt*16 + nt*4 + 0], C[mt*16 + nt*4 + 1]);
                *(float2*)(bw + rb * 36 + 8 * nt + 2 * t) =
                    make_float2(C[mt*16 + nt*4 + 2], C[mt*16 + nt*4 + 3]);
            }
        __syncwarp();
        {
            int rbase = r0 + wrow;
            float s = 0.f, q = 0.f;
#pragma unroll 4
            for (int rl = 0; rl < 32; rl++) {
                float m = (ch == 0) ? 1.f : ((((rbase + rl) & 511) != 511) ? 1.f : 0.f);
                float v = bw[rl * 36 + lane] * m;
                s += v; q += v * v;
            }
            smf[WS_F + ((ch * 2 + 0) * 4 + warp) * 32 + lane] = s;
            smf[WS_F + ((ch * 2 + 1) * 4 + warp) * 32 + lane] = q;
        }
        if (ch == 0) {
#pragma unroll
            for (int i = 0; i < 8; i++) {
                int rl = 4 * i + (lane >> 3);
                int cc = (lane & 7) * 4;
                float4 v = *(const float4*)(bw + rl * 36 + cc);
                *(float4*)(dout + (size_t)(r0 + wrow + rl) * 32 + cc) = v;
            }
        } else {
            float* dst = (ch == 1) ? g_cf : g_cb;
#pragma unroll
            for (int i = 0; i < 8; i++) {
                int rl = 4 * i + (lane >> 3);
                int gr = r0 + wrow + rl;
                if ((gr & 511) != 511) {
                    int e = gr - (gr >> 9);
                    int cc = (lane & 7) * 4;
                    float4 v = *(const float4*)(bw + rl * 36 + cc);
                    *(float4*)(dst + (size_t)e * 32 + cc) = v;
                }
            }
        }
    }

    __syncthreads();
    for (int idx = tid; idx < 192; idx += 128) {
        int ch = idx / 64, st = (idx >> 5) & 1, c = idx & 31;
        float a = 0.f;
#pragma unroll
        for (int w = 0; w < 4; w++) a += smf[WS_F + ((ch * 2 + st) * 4 + w) * 32 + c];
        g_epart[ch][st][c][bid] = a;
    }
}

// ---------------- stats finalize ----------------
__global__ void k_fin_edge(const float* __restrict__ gamma, const float* __restrict__ beta) {
    int arr = blockIdx.x >> 5, c = blockIdx.x & 31;
    int tid = threadIdx.x;
    __shared__ double ss[256], sq[256];
    double sa = 0.0, sb2 = 0.0, qa = 0.0, qb = 0.0;
    const float* ps = &g_epart[arr][0][c][0];
    const float* pz = &g_epart[arr][1][c][0];
    for (int i = tid; i < NB1; i += 512) {
        sa += ps[i]; qa += pz[i];
        if (i + 256 < NB1) { sb2 += ps[i + 256]; qb += pz[i + 256]; }
    }
    ss[tid] = sa + sb2; sq[tid] = qa + qb;
    __syncthreads();
    for (int o = 128; o > 0; o >>= 1) {
        if (tid < o) { ss[tid] += ss[tid + o]; sq[tid] += sq[tid + o]; }
        __syncthreads();
    }
    if (tid == 0) {
        double M   = (arr == 0) ? (double)ROWS_C : (double)ER_C;
        double mu  = ss[0] / M;
        double var = sq[0] / M - mu * mu;
        double inv = 1.0 / sqrt(var + BN_EPS);
        g_escale[arr][c] = (float)((double)gamma[c] * inv);
        g_ebias [arr][c] = (float)((double)beta[c] - mu * (double)gamma[c] * inv);
    }
}

__global__ void k_fin_node(const float* __restrict__ gamma, const float* __restrict__ beta) {
    int c = blockIdx.x;
    int tid = threadIdx.x;
    __shared__ double ss[256], sq[256];
    double sa = 0.0, sb2 = 0.0, qa = 0.0, qb = 0.0;
    const float* ps = &g_npart[0][c][0];
    const float* pz = &g_npart[1][c][0];
    for (int i = tid; i < NB2; i += 512) {
        sa += ps[i]; qa += pz[i];
        if (i + 256 < NB2) { sb2 += ps[i + 256]; qb += pz[i + 256]; }
    }
    ss[tid] = sa + sb2; sq[tid] = qa + qb;
    __syncthreads();
    for (int o = 128; o > 0; o >>= 1) {
        if (tid < o) { ss[tid] += ss[tid + o]; sq[tid] += sq[tid + o]; }
        __syncthreads();
    }
    if (tid == 0) {
        double M   = (double)ROWS_C;
        double mu  = ss[0] / M;
        double var = sq[0] / M - mu * mu;
        double inv = 1.0 / sqrt(var + BN_EPS);
        g_nscale[c] = (float)((double)gamma[c] * inv);
        g_nbias [c] = (float)((double)beta[c] - mu * (double)gamma[c] * inv);
    }
}

// ---------------- K2 (FFMA path, unchanged from R12) ----------------
__device__ __forceinline__ u64 pk(float x, float y) {
    u64 d; asm("mov.b64 %0, {%1, %2};" : "=l"(d) : "f"(x), "f"(y)); return d;
}
__device__ __forceinline__ void upk(u64 v, float& lo, float& hi) {
    asm("mov.b64 {%0, %1}, %2;" : "=f"(lo), "=f"(hi) : "l"(v));
}
__device__ __forceinline__ u64 fma2(u64 a, u64 b, u64 c) {
    u64 d; asm("fma.rn.f32x2 %0, %1, %2, %3;" : "=l"(d) : "l"(a), "l"(b), "l"(c)); return d;
}

__device__ __forceinline__ void accum_row(const u64* __restrict__ wrow, int c_g,
                                          float a0, float a1, float a2, float a3, u64* h) {
    ulonglong2 wA = *reinterpret_cast<const ulonglong2*>(wrow + c_g * 4);
    ulonglong2 wB = *reinterpret_cast<const ulonglong2*>(wrow + c_g * 4 + 2);
    u64 x;
    x = pk(a0, a0); h[0] = fma2(x, wA.x, h[0]); h[1] = fma2(x, wA.y, h[1]);
                    h[2] = fma2(x, wB.x, h[2]); h[3] = fma2(x, wB.y, h[3]);
    x = pk(a1, a1); h[4] = fma2(x, wA.x, h[4]); h[5] = fma2(x, wA.y, h[5]);
                    h[6] = fma2(x, wB.x, h[6]); h[7] = fma2(x, wB.y, h[7]);
    x = pk(a2, a2); h[8] = fma2(x, wA.x, h[8]); h[9] = fma2(x, wA.y, h[9]);
                    h[10] = fma2(x, wB.x, h[10]); h[11] = fma2(x, wB.y, h[11]);
    x = pk(a3, a3); h[12] = fma2(x, wA.x, h[12]); h[13] = fma2(x, wA.y, h[13]);
                    h[14] = fma2(x, wB.x, h[14]); h[15] = fma2(x, wB.y, h[15]);
}

__device__ __forceinline__ void gemm32(const float* __restrict__ As,
                                       const u64* __restrict__ W, const u64* __restrict__ B,
                                       int r_g, int c_g, u64* h) {
#pragma unroll
    for (int cp = 0; cp < 4; cp++) {
        u64 v = B[c_g * 4 + cp];
        h[cp] = v; h[4 + cp] = v; h[8 + cp] = v; h[12 + cp] = v;
    }
#pragma unroll 4
    for (int k = 0; k < 32; k++) {
        float4 tv = *reinterpret_cast<const float4*>(As + k * 36 + 4 * r_g);
        accum_row(W + k * 16, c_g, tv.x, tv.y, tv.z, tv.w, h);
    }
}

__device__ __forceinline__ void unpack_tile(const u64* h, float o[4][8], bool relu) {
#pragma unroll
    for (int r = 0; r < 4; r++)
#pragma unroll
        for (int cp = 0; cp < 4; cp++) {
            float lo, hi; upk(h[r * 4 + cp], lo, hi);
            o[r][2 * cp]     = relu ? lrelu(lo) : lo;
            o[r][2 * cp + 1] = relu ? lrelu(hi) : hi;
        }
}

__device__ __forceinline__ void stage_tile(float* As, int r_g, int c_g, const float o[4][8]) {
    __syncwarp();
#pragma unroll
    for (int cc = 0; cc < 8; cc++) {
        *reinterpret_cast<float4*>(As + (8 * c_g + cc) * 36 + 4 * r_g) =
            make_float4(o[0][cc], o[1][cc], o[2][cc], o[3][cc]);
    }
    __syncwarp();
}

__device__ __forceinline__ void mlp_tail(float* As,
                                         const u64* W2, const u64* B2,
                                         const u64* W3, const u64* B3,
                                         int r_g, int c_g, u64* h) {
    float o[4][8];
    unpack_tile(h, o, true);
    stage_tile(As, r_g, c_g, o);
    gemm32(As, W2, B2, r_g, c_g, h);
    unpack_tile(h, o, true);
    stage_tile(As, r_g, c_g, o);
    gemm32(As, W3, B3, r_g, c_g, h);
}

__device__ __forceinline__ void warp_stats(const float o[4][8], const float m[4],
                                           int lane, int c_g, float* wsS, float* wsQ) {
    float s[8], q[8];
#pragma unroll
    for (int cc = 0; cc < 8; cc++) { s[cc] = 0.f; q[cc] = 0.f; }
#pragma unroll
    for (int r = 0; r < 4; r++)
#pragma unroll
        for (int cc = 0; cc < 8; cc++) {
            float v = o[r][cc] * m[r];
            s[cc] += v; q[cc] += v * v;
        }
#pragma unroll
    for (int msk = 4; msk <= 16; msk <<= 1)
#pragma unroll
        for (int cc = 0; cc < 8; cc++) {
            s[cc] += __shfl_xor_sync(0xffffffffu, s[cc], msk);
            q[cc] += __shfl_xor_sync(0xffffffffu, q[cc], msk);
        }
    if (lane < 4) {
#pragma unroll
        for (int cc = 0; cc < 8; cc++) { wsS[8 * c_g + cc] = s[cc]; wsQ[8 * c_g + cc] = q[cc]; }
    }
}

__global__ __launch_bounds__(256, 2) void k_node(
    float* __restrict__ dout,
    const float* __restrict__ nW1, const float* __restrict__ nb1,
    const float* __restrict__ nW2, const float* __restrict__ nb2,
    const float* __restrict__ nW3, const float* __restrict__ nb3)
{
    extern __shared__ float sm[];
    const int tid = threadIdx.x, bid = blockIdx.x;
    for (int i = tid; i < 3360; i += 256) {
        float v;
        if      (i < 1024) v = nW1[i];
        else if (i < 1056) v = nb1[i - 1024];
        else if (i < 2080) v = nW2[i - 1056];
        else if (i < 2112) v = nb2[i - 2080];
        else if (i < 3136) v = nW3[i - 2112];
        else if (i < 3168) v = nb3[i - 3136];
        else {
            int k = i - 3168;
            int arr = k / 64, sb3 = (k >> 5) & 1, c = k & 31;
            v = sb3 ? g_ebias[arr][c] : g_escale[arr][c];
        }
        sm[i] = v;
    }
    __syncthreads();

    const u64* nW1s = (const u64*)(sm);
    const u64* nB1s = (const u64*)(sm + 1024);
    const u64* nW2s = (const u64*)(sm + 1056);
    const u64* nB2s = (const u64*)(sm + 2080);
    const u64* nW3s = (const u64*)(sm + 2112);
    const u64* nB3s = (const u64*)(sm + 3136);
    const float* s0 = sm + 3168; const float* b0 = sm + 3200;
    const float* s1 = sm + 3232; const float* b1 = sm + 3264;
    const float* s2 = sm + 3296; const float* b2 = sm + 3328;

    int lane = tid & 31, warp = tid >> 5;
    int r_g = lane >> 2, c_g = lane & 3;
    float* Asw = sm + N_A + warp * 1152;
    int r0 = bid * 256 + warp * 32;
    int n0 = bid >> 1;
    int c0 = 8 * c_g;

    float agg[4][8];
    float o[4][8];

#pragma unroll
    for (int rr = 0; rr < 4; rr++) {
        int r = r0 + 4 * r_g + rr;
        int t = r & 511;
        float mf = (t != 0)   ? 1.f : 0.f;
        float mb = (t != 511) ? 1.f : 0.f;

        const float4* ip = reinterpret_cast<const float4*>(dout) + (size_t)r * 8 + c_g * 2;
        float4 va = ip[0], vb = ip[1];
        agg[rr][0] = s0[c0+0]*va.x + b0[c0+0]; agg[rr][1] = s0[c0+1]*va.y + b0[c0+1];
        agg[rr][2] = s0[c0+2]*va.z + b0[c0+2]; agg[rr][3] = s0[c0+3]*va.w + b0[c0+3];
        agg[rr][4] = s0[c0+4]*vb.x + b0[c0+4]; agg[rr][5] = s0[c0+5]*vb.y + b0[c0+5];
        agg[rr][6] = s0[c0+6]*vb.z + b0[c0+6]; agg[rr][7] = s0[c0+7]*vb.w + b0[c0+7];

        {
            long e = (long)r - n0 - 1; if (e < 0) e = 0;
            const float4* fp = reinterpret_cast<const float4*>(g_cf + (size_t)e * 32 + c0);
            float4 fa = fp[0], fb = fp[1];
            agg[rr][0] += mf * (s1[c0+0]*fa.x + b1[c0+0]);
            agg[rr][1] += mf * (s1[c0+1]*fa.y + b1[c0+1]);
            agg[rr][2] += mf * (s1[c0+2]*fa.z + b1[c0+2]);
            agg[rr][3] += mf * (s1[c0+3]*fa.w + b1[c0+3]);
            agg[rr][4] += mf * (s1[c0+4]*fb.x + b1[c0+4]);
            agg[rr][5] += mf * (s1[c0+5]*fb.y + b1[c0+5]);
            agg[rr][6] += mf * (s1[c0+6]*fb.z + b1[c0+6]);
            agg[rr][7] += mf * (s1[c0+7]*fb.w + b1[c0+7]);
        }
        {
            long e = (long)r - n0; if (e > ER_C - 1) e = ER_C - 1;
            const float4* bp = reinterpret_cast<const float4*>(g_cb + (size_t)e * 32 + c0);
            float4 ba = bp[0], bb = bp[1];
            agg[rr][0] += mb * (s2[c0+0]*ba.x + b2[c0+0]);
            agg[rr][1] += mb * (s2[c0+1]*ba.y + b2[c0+1]);
            agg[rr][2] += mb * (s2[c0+2]*ba.z + b2[c0+2]);
            agg[rr][3] += mb * (s2[c0+3]*ba.w + b2[c0+3]);
            agg[rr][4] += mb * (s2[c0+4]*bb.x + b2[c0+4]);
            agg[rr][5] += mb * (s2[c0+5]*bb.y + b2[c0+5]);
            agg[rr][6] += mb * (s2[c0+6]*bb.z + b2[c0+6]);
            agg[rr][7] += mb * (s2[c0+7]*bb.w + b2[c0+7]);
        }
    }

    u64 h[16];
    stage_tile(Asw, r_g, c_g, agg);
    gemm32(Asw, nW1s, nB1s, r_g, c_g, h);
    mlp_tail(Asw, nW2s, nB2s, nW3s, nB3s, r_g, c_g, h);
    unpack_tile(h, o, false);
#pragma unroll
    for (int rr = 0; rr < 4; rr++) {
        float4* p = reinterpret_cast<float4*>(dout) + (size_t)(r0 + 4 * r_g + rr) * 8 + c_g * 2;
        p[0] = make_float4(o[rr][0], o[rr][1], o[rr][2], o[rr][3]);
        p[1] = make_float4(o[rr][4], o[rr][5], o[rr][6], o[rr][7]);
    }
    {
        float mall[4] = {1.f, 1.f, 1.f, 1.f};
        warp_stats(o, mall, lane, c_g, sm + N_WS + (0 * 8 + warp) * 32, sm + N_WS + (1 * 8 + warp) * 32);
    }

    __syncthreads();
    if (tid < 64) {
        int st = tid >> 5, c = tid & 31;
        float a = 0.f;
#pragma unroll
        for (int w = 0; w < 8; w++) a += sm[N_WS + (st * 8 + w) * 32 + c];
        g_npart[st][c][bid] = a;
    }
}

// ---------------- K3: normalize in place ----------------
__global__ __launch_bounds__(256) void k_final(float* __restrict__ dout) {
    __shared__ float sc[32], bi[32];
    int tid = threadIdx.x;
    if (tid < 32) { sc[tid] = g_nscale[tid]; bi[tid] = g_nbias[tid]; }
    __syncthreads();
    int lane = tid & 31;
    int s = lane & 3;
    int r = (blockIdx.x * 256 + tid) >> 2;
    int c0 = s * 8;
    float4* D4 = reinterpret_cast<float4*>(dout);
    float4 va = D4[(size_t)r * 8 + s * 2];
    float4 vb = D4[(size_t)r * 8 + s * 2 + 1];
    va.x = va.x * sc[c0 + 0] + bi[c0 + 0]; va.y = va.y * sc[c0 + 1] + bi[c0 + 1];
    va.z = va.z * sc[c0 + 2] + bi[c0 + 2]; va.w = va.w * sc[c0 + 3] + bi[c0 + 3];
    vb.x = vb.x * sc[c0 + 4] + bi[c0 + 4]; vb.y = vb.y * sc[c0 + 5] + bi[c0 + 5];
    vb.z = vb.z * sc[c0 + 6] + bi[c0 + 6]; vb.w = vb.w * sc[c0 + 7] + bi[c0 + 7];
    D4[(size_t)r * 8 + s * 2]     = va;
    D4[(size_t)r * 8 + s * 2 + 1] = vb;
}

// ---------------- launch ----------------
extern "C" void kernel_launch(void* const* d_in, const int* in_sizes, int n_in,
                              void* d_out, int out_size)
{
    const float* x    = (const float*)d_in[0];
    const float* eW1  = (const float*)d_in[1];
    const float* eb1  = (const float*)d_in[2];
    const float* eW2  = (const float*)d_in[3];
    const float* eb2  = (const float*)d_in[4];
    const float* eW3  = (const float*)d_in[5];
    const float* eb3  = (const float*)d_in[6];
    const float* eg   = (const float*)d_in[7];
    const float* ebt  = (const float*)d_in[8];
    const float* nW1  = (const float*)d_in[9];
    const float* nb1  = (const float*)d_in[10];
    const float* nW2  = (const float*)d_in[11];
    const float* nb2  = (const float*)d_in[12];
    const float* nW3  = (const float*)d_in[13];
    const float* nb3  = (const float*)d_in[14];
    const float* ng   = (const float*)d_in[15];
    const float* nbt  = (const float*)d_in[16];
    float* out = (float*)d_out;

    cudaFuncSetAttribute(k_edge_tc, cudaFuncAttributeMaxDynamicSharedMemorySize, K1_TOT * 4);
    cudaFuncSetAttribute(k_node, cudaFuncAttributeMaxDynamicSharedMemorySize, N_TOT * 4);

    k_edge_tc<<<NB1, 128, K1_TOT * 4>>>(x, out, eW1, eb1, eW2, eb2, eW3, eb3);
    k_fin_edge<<<96, 256>>>(eg, ebt);
    k_node<<<NB2, 256, N_TOT * 4>>>(out, nW1, nb1, nW2, nb2, nW3, nb3);
    k_fin_node<<<32, 256>>>(ng, nbt);
    k_final<<<ROWS_C * 4 / 256, 256>>>(out);
}

// round 15
// speedup vs baseline: 2.4352x; 1.0821x over previous
#include <cuda_runtime.h>
#include <cuda_bf16.h>
#include <cstdint>
#include <cstdlib>

// Eager module loading: __device__ globals allocated at context init.
__attribute__((constructor)) static void _force_eager_loading() {
    setenv("CUDA_MODULE_LOADING", "EAGER", 1);
}

#define NN     2048
#define TT     512
#define ROWS_C (NN*TT)        /* 1048576 */
#define ER_C   (NN*(TT-1))    /* 1046528 */
#define BN_EPS 1e-5

#define NB1    8192           /* K1 blocks, 128 rows each */
#define NB2    8192           /* K2 blocks, 128 rows each */

typedef unsigned long long u64;

// ---- K1 smem float offsets ----
#define WF_U   0
#define BIAS_F 3584
#define XS_F   3744
#define BO_F   5808
#define WS_F   10416
#define K1_TOT 11184          /* 44736 B */
#define BLK_WC_H 0
#define BLK_WC_L 1
#define BLK_W1_H 2
#define BLK_W1_L 4
#define BLK_W2_H 6
#define BLK_W2_L 8
#define BLK_W3_H 10
#define BLK_W3_L 12

// ---- K2 (HMMA) smem float offsets ----
// frag tables 0..3072 (12 blocks x 256 u32), bias 3072..3168 (b1,b2,b3),
// edge scale/bias 3168..3360, bounce 3360..7968 (4 x 1152), WS 7968..8224
#define NBLK_W1_H 0
#define NBLK_W1_L 2
#define NBLK_W2_H 4
#define NBLK_W2_L 6
#define NBLK_W3_H 8
#define NBLK_W3_L 10
#define NW_BIAS_F 3072
#define NW_SBE_F  3168
#define NW_BO_F   3360
#define NW_WS_F   7968
#define NK2_TOT   8224        /* 32896 B */

// ---- device scratch ----
__device__ float g_cf[(size_t)ER_C * 32];
__device__ float g_cb[(size_t)ER_C * 32];
__device__ float g_epart[3][2][32][NB1];
__device__ float g_npart[2][32][NB2];
__device__ float g_escale[3][32], g_ebias[3][32];
__device__ float g_nscale[32],    g_nbias[32];

__device__ __forceinline__ float lrelu(float x) { return fmaxf(x, 0.01f * x); }

// ---- bf16 split helpers ----
__device__ __forceinline__ void bsplit(float v, unsigned short& h, unsigned short& l) {
    __nv_bfloat16 hb = __float2bfloat16_rn(v);
    float rest = v - __bfloat162float(hb);
    __nv_bfloat16 lb = __float2bfloat16_rn(rest);
    h = __bfloat16_as_ushort(hb);
    l = __bfloat16_as_ushort(lb);
}
__device__ __forceinline__ void split_pack2(float v0, float v1, uint32_t& hp, uint32_t& lp) {
    unsigned short h0, l0, h1, l1;
    bsplit(v0, h0, l0); bsplit(v1, h1, l1);
    hp = (uint32_t)h0 | ((uint32_t)h1 << 16);
    lp = (uint32_t)l0 | ((uint32_t)l1 << 16);
}

// ---- HMMA m16n8k16 bf16 ----
__device__ __forceinline__ void mma4(float* c, const uint32_t* a, uint32_t b0, uint32_t b1) {
    asm volatile(
        "mma.sync.aligned.m16n8k16.row.col.f32.bf16.bf16.f32 "
        "{%0,%1,%2,%3}, {%4,%5,%6,%7}, {%8,%9}, {%0,%1,%2,%3};"
        : "+f"(c[0]), "+f"(c[1]), "+f"(c[2]), "+f"(c[3])
        : "r"(a[0]), "r"(a[1]), "r"(a[2]), "r"(a[3]), "r"(b0), "r"(b1));
}

// one K16-chunk of a 32xN32 layer; 3-product bf16 split
__device__ __forceinline__ void gemm_kc(const uint32_t* __restrict__ WFu,
        int blkH, int blkL, int kc,
        const uint32_t* aH, const uint32_t* aL, int lane, float* C)
{
    const uint4* ph = (const uint4*)(WFu + (blkH + kc) * 256 + lane * 4);
    const uint4* pl = (const uint4*)(WFu + (blkL + kc) * 256 + lane * 4);
    uint4 H0 = ph[0], H1 = ph[32];
    uint4 L0 = pl[0], L1 = pl[32];
#pragma unroll
    for (int mt = 0; mt < 2; mt++) {
        const uint32_t* ah = aH + mt * 4;
        const uint32_t* al = aL + mt * 4;
        float* c = C + mt * 16;
        mma4(c + 0,  ah, H0.x, H0.y); mma4(c + 0,  al, H0.x, H0.y); mma4(c + 0,  ah, L0.x, L0.y);
        mma4(c + 4,  ah, H0.z, H0.w); mma4(c + 4,  al, H0.z, H0.w); mma4(c + 4,  ah, L0.z, L0.w);
        mma4(c + 8,  ah, H1.x, H1.y); mma4(c + 8,  al, H1.x, H1.y); mma4(c + 8,  ah, L1.x, L1.y);
        mma4(c + 12, ah, H1.z, H1.w); mma4(c + 12, al, H1.z, H1.w); mma4(c + 12, ah, L1.z, L1.w);
    }
}

__device__ __forceinline__ void init_C(const float* bias, int t, float* C) {
#pragma unroll
    for (int nt = 0; nt < 4; nt++) {
        float b0 = bias[8 * nt + 2 * t];
        float b1 = bias[8 * nt + 2 * t + 1];
#pragma unroll
        for (int mt = 0; mt < 2; mt++) {
            C[mt*16 + nt*4 + 0] = b0; C[mt*16 + nt*4 + 1] = b1;
            C[mt*16 + nt*4 + 2] = b0; C[mt*16 + nt*4 + 3] = b1;
        }
    }
}

// relu + split C -> next-layer A frags (thread-local repack)
__device__ __forceinline__ void epi_split(const float* C, uint32_t* AH, uint32_t* AL) {
#pragma unroll
    for (int mt = 0; mt < 2; mt++)
#pragma unroll
        for (int kc = 0; kc < 2; kc++) {
            int j0 = 2 * kc, j1 = 2 * kc + 1;
            float v0 = lrelu(C[mt*16 + j0*4 + 0]), v1 = lrelu(C[mt*16 + j0*4 + 1]);
            float v2 = lrelu(C[mt*16 + j0*4 + 2]), v3 = lrelu(C[mt*16 + j0*4 + 3]);
            float u0 = lrelu(C[mt*16 + j1*4 + 0]), u1 = lrelu(C[mt*16 + j1*4 + 1]);
            float u2 = lrelu(C[mt*16 + j1*4 + 2]), u3 = lrelu(C[mt*16 + j1*4 + 3]);
            split_pack2(v0, v1, AH[kc*8 + mt*4 + 0], AL[kc*8 + mt*4 + 0]);
            split_pack2(v2, v3, AH[kc*8 + mt*4 + 1], AL[kc*8 + mt*4 + 1]);
            split_pack2(u0, u1, AH[kc*8 + mt*4 + 2], AL[kc*8 + mt*4 + 2]);
            split_pack2(u2, u3, AH[kc*8 + mt*4 + 3], AL[kc*8 + mt*4 + 3]);
        }
}

// ---------------- K1: HMMA edge chains (R14 winner, unchanged) ----------------
__global__ __launch_bounds__(128, 3) void k_edge_tc(
    const float* __restrict__ x, float* __restrict__ dout,
    const float* __restrict__ eW1, const float* __restrict__ eb1,
    const float* __restrict__ eW2, const float* __restrict__ eb2,
    const float* __restrict__ eW3, const float* __restrict__ eb3)
{
    extern __shared__ float smf[];
    uint32_t* WFu = (uint32_t*)smf;
    const int tid = threadIdx.x, bid = blockIdx.x;
    const int lane = tid & 31, warp = tid >> 5;
    const int g = lane >> 2, t = lane & 3;
    const int r0 = bid * 128;

    if (tid < 32) {
        float b1v = eb1[tid], wd = eW1[1024 + tid];
        smf[BIAS_F + tid]       = b1v;
        smf[BIAS_F + 32 + tid]  = b1v + wd;
        smf[BIAS_F + 64 + tid]  = b1v - wd;
        smf[BIAS_F + 96 + tid]  = eb2[tid];
        smf[BIAS_F + 128 + tid] = eb3[tid];
    }
    for (int idx = tid; idx < 129 * 16; idx += 128) {
        int row = r0 + (idx >> 4);
        if (row > ROWS_C - 1) row = ROWS_C - 1;
        smf[XS_F + idx] = x[(size_t)row * 16 + (idx & 15)];
    }
    for (int idx = tid; idx < 3584; idx += 128) {
        int blk = idx >> 8;
        int rem = idx & 255;
        int j4 = rem >> 7;
        int ln = (rem >> 2) & 31;
        int q  = rem & 3;
        int gg = ln >> 2, tt = ln & 3;
        int nt = 2 * j4 + (q >> 1);
        int rg = q & 1;
        int n  = 8 * nt + gg;
        int half, kc, which;
        if (blk < 2)       { which = 0; half = blk;          kc = 0; }
        else if (blk < 6)  { which = 1; half = (blk - 2) >> 1;  kc = (blk - 2) & 1; }
        else if (blk < 10) { which = 2; half = (blk - 6) >> 1;  kc = (blk - 6) & 1; }
        else               { which = 3; half = (blk - 10) >> 1; kc = (blk - 10) & 1; }
        int k0 = 16 * kc + 2 * tt + 8 * rg;
        float w0, w1;
        if (which == 0)      { w0 = eW1[k0*32+n] + eW1[(k0+16)*32+n];
                               w1 = eW1[(k0+1)*32+n] + eW1[(k0+17)*32+n]; }
        else if (which == 1) { w0 = eW1[k0*32+n]; w1 = eW1[(k0+1)*32+n]; }
        else if (which == 2) { w0 = eW2[k0*32+n]; w1 = eW2[(k0+1)*32+n]; }
        else                 { w0 = eW3[k0*32+n]; w1 = eW3[(k0+1)*32+n]; }
        unsigned short h0, l0, h1, l1;
        bsplit(w0, h0, l0); bsplit(w1, h1, l1);
        WFu[blk * 256 + j4 * 128 + ln * 4 + q] =
            (half == 0) ? ((uint32_t)h0 | ((uint32_t)h1 << 16))
                        : ((uint32_t)l0 | ((uint32_t)l1 << 16));
    }
    __syncthreads();

    const int wrow = warp * 32;
    float* bw = smf + BO_F + warp * 1152;

    uint32_t XcH[8], XcL[8], XnH[8], XnL[8];
#pragma unroll
    for (int mt = 0; mt < 2; mt++)
#pragma unroll
        for (int rr = 0; rr < 2; rr++) {
            int rl = wrow + mt * 16 + rr * 8 + g;
            float2 vA = *(const float2*)(smf + XS_F + rl * 16 + 2 * t);
            float2 vB = *(const float2*)(smf + XS_F + rl * 16 + 2 * t + 8);
            split_pack2(vA.x, vA.y, XcH[mt*4 + rr],     XcL[mt*4 + rr]);
            split_pack2(vB.x, vB.y, XcH[mt*4 + 2 + rr], XcL[mt*4 + 2 + rr]);
            float2 nA = *(const float2*)(smf + XS_F + (rl + 1) * 16 + 2 * t);
            float2 nB = *(const float2*)(smf + XS_F + (rl + 1) * 16 + 2 * t + 8);
            split_pack2(nA.x, nA.y, XnH[mt*4 + rr],     XnL[mt*4 + rr]);
            split_pack2(nB.x, nB.y, XnH[mt*4 + 2 + rr], XnL[mt*4 + 2 + rr]);
        }

    uint32_t A2H[16], A2L[16];
    float C[32];

#pragma unroll
    for (int ch = 0; ch < 3; ch++) {
        init_C(smf + BIAS_F + ch * 32, t, C);
        if (ch == 0) {
            gemm_kc(WFu, BLK_WC_H, BLK_WC_L, 0, XcH, XcL, lane, C);
        } else if (ch == 1) {
            gemm_kc(WFu, BLK_W1_H, BLK_W1_L, 0, XnH, XnL, lane, C);
            gemm_kc(WFu, BLK_W1_H, BLK_W1_L, 1, XcH, XcL, lane, C);
        } else {
            gemm_kc(WFu, BLK_W1_H, BLK_W1_L, 0, XcH, XcL, lane, C);
            gemm_kc(WFu, BLK_W1_H, BLK_W1_L, 1, XnH, XnL, lane, C);
        }
        epi_split(C, A2H, A2L);
        init_C(smf + BIAS_F + 96, t, C);
        gemm_kc(WFu, BLK_W2_H, BLK_W2_L, 0, A2H,     A2L,     lane, C);
        gemm_kc(WFu, BLK_W2_H, BLK_W2_L, 1, A2H + 8, A2L + 8, lane, C);
        epi_split(C, A2H, A2L);
        init_C(smf + BIAS_F + 128, t, C);
        gemm_kc(WFu, BLK_W3_H, BLK_W3_L, 0, A2H,     A2L,     lane, C);
        gemm_kc(WFu, BLK_W3_H, BLK_W3_L, 1, A2H + 8, A2L + 8, lane, C);

        __syncwarp();
#pragma unroll
        for (int mt = 0; mt < 2; mt++)
#pragma unroll
            for (int nt = 0; nt < 4; nt++) {
                int ra = mt * 16 + g, rb = ra + 8;
                *(float2*)(bw + ra * 36 + 8 * nt + 2 * t) =
                    make_float2(C[mt*16 + nt*4 + 0], C[mt*16 + nt*4 + 1]);
                *(float2*)(bw + rb * 36 + 8 * nt + 2 * t) =
                    make_float2(C[mt*16 + nt*4 + 2], C[mt*16 + nt*4 + 3]);
            }
        __syncwarp();
        {
            int rbase = r0 + wrow;
            float s = 0.f, q = 0.f;
#pragma unroll 4
            for (int rl = 0; rl < 32; rl++) {
                float m = (ch == 0) ? 1.f : ((((rbase + rl) & 511) != 511) ? 1.f : 0.f);
                float v = bw[rl * 36 + lane] * m;
                s += v; q += v * v;
            }
            smf[WS_F + ((ch * 2 + 0) * 4 + warp) * 32 + lane] = s;
            smf[WS_F + ((ch * 2 + 1) * 4 + warp) * 32 + lane] = q;
        }
        if (ch == 0) {
#pragma unroll
            for (int i = 0; i < 8; i++) {
                int rl = 4 * i + (lane >> 3);
                int cc = (lane & 7) * 4;
                float4 v = *(const float4*)(bw + rl * 36 + cc);
                *(float4*)(dout + (size_t)(r0 + wrow + rl) * 32 + cc) = v;
            }
        } else {
            float* dst = (ch == 1) ? g_cf : g_cb;
#pragma unroll
            for (int i = 0; i < 8; i++) {
                int rl = 4 * i + (lane >> 3);
                int gr = r0 + wrow + rl;
                if ((gr & 511) != 511) {
                    int e = gr - (gr >> 9);
                    int cc = (lane & 7) * 4;
                    float4 v = *(const float4*)(bw + rl * 36 + cc);
                    *(float4*)(dst + (size_t)e * 32 + cc) = v;
                }
            }
        }
    }

    __syncthreads();
    for (int idx = tid; idx < 192; idx += 128) {
        int ch = idx / 64, st = (idx >> 5) & 1, c = idx & 31;
        float a = 0.f;
#pragma unroll
        for (int w = 0; w < 4; w++) a += smf[WS_F + ((ch * 2 + st) * 4 + w) * 32 + c];
        g_epart[ch][st][c][bid] = a;
    }
}

// ---------------- stats finalize ----------------
__global__ void k_fin_edge(const float* __restrict__ gamma, const float* __restrict__ beta) {
    int arr = blockIdx.x >> 5, c = blockIdx.x & 31;
    int tid = threadIdx.x;
    __shared__ double ss[256], sq[256];
    double sa = 0.0, sb2 = 0.0, qa = 0.0, qb = 0.0;
    const float* ps = &g_epart[arr][0][c][0];
    const float* pz = &g_epart[arr][1][c][0];
    for (int i = tid; i < NB1; i += 512) {
        sa += ps[i]; qa += pz[i];
        if (i + 256 < NB1) { sb2 += ps[i + 256]; qb += pz[i + 256]; }
    }
    ss[tid] = sa + sb2; sq[tid] = qa + qb;
    __syncthreads();
    for (int o = 128; o > 0; o >>= 1) {
        if (tid < o) { ss[tid] += ss[tid + o]; sq[tid] += sq[tid + o]; }
        __syncthreads();
    }
    if (tid == 0) {
        double M   = (arr == 0) ? (double)ROWS_C : (double)ER_C;
        double mu  = ss[0] / M;
        double var = sq[0] / M - mu * mu;
        double inv = 1.0 / sqrt(var + BN_EPS);
        g_escale[arr][c] = (float)((double)gamma[c] * inv);
        g_ebias [arr][c] = (float)((double)beta[c] - mu * (double)gamma[c] * inv);
    }
}

__global__ void k_fin_node(const float* __restrict__ gamma, const float* __restrict__ beta) {
    int c = blockIdx.x;
    int tid = threadIdx.x;
    __shared__ double ss[256], sq[256];
    double sa = 0.0, sb2 = 0.0, qa = 0.0, qb = 0.0;
    const float* ps = &g_npart[0][c][0];
    const float* pz = &g_npart[1][c][0];
    for (int i = tid; i < NB2; i += 512) {
        sa += ps[i]; qa += pz[i];
        if (i + 256 < NB2) { sb2 += ps[i + 256]; qb += pz[i + 256]; }
    }
    ss[tid] = sa + sb2; sq[tid] = qa + qb;
    __syncthreads();
    for (int o = 128; o > 0; o >>= 1) {
        if (tid < o) { ss[tid] += ss[tid + o]; sq[tid] += sq[tid + o]; }
        __syncthreads();
    }
    if (tid == 0) {
        double M   = (double)ROWS_C;
        double mu  = ss[0] / M;
        double var = sq[0] / M - mu * mu;
        double inv = 1.0 / sqrt(var + BN_EPS);
        g_nscale[c] = (float)((double)gamma[c] * inv);
        g_nbias [c] = (float)((double)beta[c] - mu * (double)gamma[c] * inv);
    }
}

// ---------------- K2: HMMA aggregate + node MLP ----------------
__global__ __launch_bounds__(128, 3) void k_node_tc(
    float* __restrict__ dout,
    const float* __restrict__ nW1, const float* __restrict__ nb1,
    const float* __restrict__ nW2, const float* __restrict__ nb2,
    const float* __restrict__ nW3, const float* __restrict__ nb3)
{
    extern __shared__ float smf[];
    uint32_t* WFu = (uint32_t*)smf;
    const int tid = threadIdx.x, bid = blockIdx.x;
    const int lane = tid & 31, warp = tid >> 5;
    const int g = lane >> 2, t = lane & 3;

    if (tid < 32) {
        smf[NW_BIAS_F + tid]      = nb1[tid];
        smf[NW_BIAS_F + 32 + tid] = nb2[tid];
        smf[NW_BIAS_F + 64 + tid] = nb3[tid];
    }
    for (int i = tid; i < 192; i += 128) {
        int arr = i / 64, sb3 = (i >> 5) & 1, c = i & 31;
        smf[NW_SBE_F + i] = sb3 ? g_ebias[arr][c] : g_escale[arr][c];
    }
    // weight frag tables: 12 blocks (W1,W2,W3 x hi/lo x 2kc)
    for (int idx = tid; idx < 3072; idx += 128) {
        int blk = idx >> 8;
        int rem = idx & 255;
        int j4 = rem >> 7;
        int ln = (rem >> 2) & 31;
        int q  = rem & 3;
        int gg = ln >> 2, tt = ln & 3;
        int nt = 2 * j4 + (q >> 1);
        int rg = q & 1;
        int n  = 8 * nt + gg;
        int which = blk >> 2;           // 0..2
        int sub = blk & 3;
        int half = sub >> 1, kc = sub & 1;
        int k0 = 16 * kc + 2 * tt + 8 * rg;
        const float* W = (which == 0) ? nW1 : (which == 1) ? nW2 : nW3;
        float w0 = W[k0 * 32 + n], w1 = W[(k0 + 1) * 32 + n];
        unsigned short h0, l0, h1, l1;
        bsplit(w0, h0, l0); bsplit(w1, h1, l1);
        WFu[blk * 256 + j4 * 128 + ln * 4 + q] =
            (half == 0) ? ((uint32_t)h0 | ((uint32_t)h1 << 16))
                        : ((uint32_t)l0 | ((uint32_t)l1 << 16));
    }
    __syncthreads();

    const float* s0 = smf + NW_SBE_F;       const float* b0 = smf + NW_SBE_F + 32;
    const float* s1 = smf + NW_SBE_F + 64;  const float* b1 = smf + NW_SBE_F + 96;
    const float* s2 = smf + NW_SBE_F + 128; const float* b2 = smf + NW_SBE_F + 160;

    const int wrow = warp * 32;
    const int r0w = bid * 128 + wrow;
    const int n0 = bid >> 2;               // 128-row blocks: 4 per sequence
    float* bw = smf + NW_BO_F + warp * 1152;
    const int c0 = 8 * t;                  // agg: lane covers rows 4g..4g+3, cols 8t..8t+7

    // ---- aggregation into bounce ----
#pragma unroll
    for (int rr = 0; rr < 4; rr++) {
        int rl = 4 * g + rr;
        int r = r0w + rl;
        int tt2 = r & 511;
        float mf = (tt2 != 0)   ? 1.f : 0.f;
        float mb = (tt2 != 511) ? 1.f : 0.f;
        float a[8];

        const float4* ip = (const float4*)dout + (size_t)r * 8 + t * 2;
        float4 va = ip[0], vb = ip[1];
        a[0] = s0[c0+0]*va.x + b0[c0+0]; a[1] = s0[c0+1]*va.y + b0[c0+1];
        a[2] = s0[c0+2]*va.z + b0[c0+2]; a[3] = s0[c0+3]*va.w + b0[c0+3];
        a[4] = s0[c0+4]*vb.x + b0[c0+4]; a[5] = s0[c0+5]*vb.y + b0[c0+5];
        a[6] = s0[c0+6]*vb.z + b0[c0+6]; a[7] = s0[c0+7]*vb.w + b0[c0+7];
        {
            long e = (long)r - n0 - 1; if (e < 0) e = 0;
            const float4* fp = (const float4*)(g_cf + (size_t)e * 32 + c0);
            float4 fa = fp[0], fb = fp[1];
            a[0] += mf * (s1[c0+0]*fa.x + b1[c0+0]);
            a[1] += mf * (s1[c0+1]*fa.y + b1[c0+1]);
            a[2] += mf * (s1[c0+2]*fa.z + b1[c0+2]);
            a[3] += mf * (s1[c0+3]*fa.w + b1[c0+3]);
            a[4] += mf * (s1[c0+4]*fb.x + b1[c0+4]);
            a[5] += mf * (s1[c0+5]*fb.y + b1[c0+5]);
            a[6] += mf * (s1[c0+6]*fb.z + b1[c0+6]);
            a[7] += mf * (s1[c0+7]*fb.w + b1[c0+7]);
        }
        {
            long e = (long)r - n0; if (e > ER_C - 1) e = ER_C - 1;
            const float4* bp = (const float4*)(g_cb + (size_t)e * 32 + c0);
            float4 ba = bp[0], bb = bp[1];
            a[0] += mb * (s2[c0+0]*ba.x + b2[c0+0]);
            a[1] += mb * (s2[c0+1]*ba.y + b2[c0+1]);
            a[2] += mb * (s2[c0+2]*ba.z + b2[c0+2]);
            a[3] += mb * (s2[c0+3]*ba.w + b2[c0+3]);
            a[4] += mb * (s2[c0+4]*bb.x + b2[c0+4]);
            a[5] += mb * (s2[c0+5]*bb.y + b2[c0+5]);
            a[6] += mb * (s2[c0+6]*bb.z + b2[c0+6]);
            a[7] += mb * (s2[c0+7]*bb.w + b2[c0+7]);
        }
        *(float4*)(bw + rl * 36 + c0)     = make_float4(a[0], a[1], a[2], a[3]);
        *(float4*)(bw + rl * 36 + c0 + 4) = make_float4(a[4], a[5], a[6], a[7]);
    }
    __syncwarp();

    // ---- A frags from bounce ----
    uint32_t AH[16], AL[16];
#pragma unroll
    for (int mt = 0; mt < 2; mt++)
#pragma unroll
        for (int rr = 0; rr < 2; rr++) {
            int rl = mt * 16 + rr * 8 + g;
#pragma unroll
            for (int kc = 0; kc < 2; kc++) {
                float2 vA = *(const float2*)(bw + rl * 36 + 16 * kc + 2 * t);
                float2 vB = *(const float2*)(bw + rl * 36 + 16 * kc + 2 * t + 8);
                split_pack2(vA.x, vA.y, AH[kc*8 + mt*4 + rr],     AL[kc*8 + mt*4 + rr]);
                split_pack2(vB.x, vB.y, AH[kc*8 + mt*4 + 2 + rr], AL[kc*8 + mt*4 + 2 + rr]);
            }
        }

    float C[32];
    init_C(smf + NW_BIAS_F, t, C);
    gemm_kc(WFu, NBLK_W1_H, NBLK_W1_L, 0, AH,     AL,     lane, C);
    gemm_kc(WFu, NBLK_W1_H, NBLK_W1_L, 1, AH + 8, AL + 8, lane, C);
    epi_split(C, AH, AL);
    init_C(smf + NW_BIAS_F + 32, t, C);
    gemm_kc(WFu, NBLK_W2_H, NBLK_W2_L, 0, AH,     AL,     lane, C);
    gemm_kc(WFu, NBLK_W2_H, NBLK_W2_L, 1, AH + 8, AL + 8, lane, C);
    epi_split(C, AH, AL);
    init_C(smf + NW_BIAS_F + 64, t, C);
    gemm_kc(WFu, NBLK_W3_H, NBLK_W3_L, 0, AH,     AL,     lane, C);
    gemm_kc(WFu, NBLK_W3_H, NBLK_W3_L, 1, AH + 8, AL + 8, lane, C);

    // ---- bounce + stats + store ----
    __syncwarp();
#pragma unroll
    for (int mt = 0; mt < 2; mt++)
#pragma unroll
        for (int nt = 0; nt < 4; nt++) {
            int ra = mt * 16 + g, rb = ra + 8;
            *(float2*)(bw + ra * 36 + 8 * nt + 2 * t) =
                make_float2(C[mt*16 + nt*4 + 0], C[mt*16 + nt*4 + 1]);
            *(float2*)(bw + rb * 36 + 8 * nt + 2 * t) =
                make_float2(C[mt*16 + nt*4 + 2], C[mt*16 + nt*4 + 3]);
        }
    __syncwarp();
    {
        float s = 0.f, q = 0.f;
#pragma unroll 4
        for (int rl = 0; rl < 32; rl++) {
            float v = bw[rl * 36 + lane];
            s += v; q += v * v;
        }
        smf[NW_WS_F + (0 * 4 + warp) * 32 + lane] = s;
        smf[NW_WS_F + (1 * 4 + warp) * 32 + lane] = q;
    }
#pragma unroll
    for (int i = 0; i < 8; i++) {
        int rl = 4 * i + (lane >> 3);
        int cc = (lane & 7) * 4;
        float4 v = *(const float4*)(bw + rl * 36 + cc);
        *(float4*)(dout + (size_t)(r0w + rl) * 32 + cc) = v;
    }

    __syncthreads();
    if (tid < 64) {
        int st = tid >> 5, c = tid & 31;
        float a = 0.f;
#pragma unroll
        for (int w = 0; w < 4; w++) a += smf[NW_WS_F + (st * 4 + w) * 32 + c];
        g_npart[st][c][bid] = a;
    }
}

// ---------------- K3: normalize in place ----------------
__global__ __launch_bounds__(256) void k_final(float* __restrict__ dout) {
    __shared__ float sc[32], bi[32];
    int tid = threadIdx.x;
    if (tid < 32) { sc[tid] = g_nscale[tid]; bi[tid] = g_nbias[tid]; }
    __syncthreads();
    int lane = tid & 31;
    int s = lane & 3;
    int r = (blockIdx.x * 256 + tid) >> 2;
    int c0 = s * 8;
    float4* D4 = reinterpret_cast<float4*>(dout);
    float4 va = D4[(size_t)r * 8 + s * 2];
    float4 vb = D4[(size_t)r * 8 + s * 2 + 1];
    va.x = va.x * sc[c0 + 0] + bi[c0 + 0]; va.y = va.y * sc[c0 + 1] + bi[c0 + 1];
    va.z = va.z * sc[c0 + 2] + bi[c0 + 2]; va.w = va.w * sc[c0 + 3] + bi[c0 + 3];
    vb.x = vb.x * sc[c0 + 4] + bi[c0 + 4]; vb.y = vb.y * sc[c0 + 5] + bi[c0 + 5];
    vb.z = vb.z * sc[c0 + 6] + bi[c0 + 6]; vb.w = vb.w * sc[c0 + 7] + bi[c0 + 7];
    D4[(size_t)r * 8 + s * 2]     = va;
    D4[(size_t)r * 8 + s * 2 + 1] = vb;
}

// ---------------- launch ----------------
extern "C" void kernel_launch(void* const* d_in, const int* in_sizes, int n_in,
                              void* d_out, int out_size)
{
    const float* x    = (const float*)d_in[0];
    const float* eW1  = (const float*)d_in[1];
    const float* eb1  = (const float*)d_in[2];
    const float* eW2  = (const float*)d_in[3];
    const float* eb2  = (const float*)d_in[4];
    const float* eW3  = (const float*)d_in[5];
    const float* eb3  = (const float*)d_in[6];
    const float* eg   = (const float*)d_in[7];
    const float* ebt  = (const float*)d_in[8];
    const float* nW1  = (const float*)d_in[9];
    const float* nb1  = (const float*)d_in[10];
    const float* nW2  = (const float*)d_in[11];
    const float* nb2  = (const float*)d_in[12];
    const float* nW3  = (const float*)d_in[13];
    const float* nb3  = (const float*)d_in[14];
    const float* ng   = (const float*)d_in[15];
    const float* nbt  = (const float*)d_in[16];
    float* out = (float*)d_out;

    cudaFuncSetAttribute(k_edge_tc, cudaFuncAttributeMaxDynamicSharedMemorySize, K1_TOT * 4);
    cudaFuncSetAttribute(k_node_tc, cudaFuncAttributeMaxDynamicSharedMemorySize, NK2_TOT * 4);

    k_edge_tc<<<NB1, 128, K1_TOT * 4>>>(x, out, eW1, eb1, eW2, eb2, eW3, eb3);
    k_fin_edge<<<96, 256>>>(eg, ebt);
    k_node_tc<<<NB2, 128, NK2_TOT * 4>>>(out, nW1, nb1, nW2, nb2, nW3, nb3);
    k_fin_node<<<32, 256>>>(ng, nbt);
    k_final<<<ROWS_C * 4 / 256, 256>>>(out);
}

// round 16
// speedup vs baseline: 3.5127x; 1.4425x over previous
#include <cuda_runtime.h>
#include <cuda_bf16.h>
#include <cstdint>
#include <cstdlib>

// Eager module loading: __device__ globals allocated at context init.
__attribute__((constructor)) static void _force_eager_loading() {
    setenv("CUDA_MODULE_LOADING", "EAGER", 1);
}

#define NN     2048
#define TT     512
#define ROWS_C (NN*TT)        /* 1048576 */
#define ER_C   (NN*(TT-1))    /* 1046528 */
#define BN_EPS 1e-5

#define TPB1   4              /* tiles (128 rows) per K1 block */
#define GRID1  (ROWS_C/(128*TPB1))   /* 2048 */
#define NB1    8192           /* stat tiles (128 rows) */
#define TPB2   4
#define GRID2  (ROWS_C/(128*TPB2))   /* 2048 */
#define NB2    8192

typedef unsigned long long u64;

// ---- K1 smem float offsets ----
// WF 0..3584, BIAS 3584..3744, XS 3744..11952 (513x16), BO 11952..16560,
// WS 16560..17328
#define BIAS_F 3584
#define XS_F   3744
#define BO_F   11952
#define WS_F   16560
#define K1_TOT 17328          /* 69312 B -> 3 blocks/SM */
#define BLK_WC_H 0
#define BLK_WC_L 1
#define BLK_W1_H 2
#define BLK_W1_L 4
#define BLK_W2_H 6
#define BLK_W2_L 8
#define BLK_W3_H 10
#define BLK_W3_L 12

// ---- K2 smem float offsets ----
#define NBLK_W1_H 0
#define NBLK_W1_L 2
#define NBLK_W2_H 4
#define NBLK_W2_L 6
#define NBLK_W3_H 8
#define NBLK_W3_L 10
#define NW_BIAS_F 3072
#define NW_SBE_F  3168
#define NW_BO_F   3360
#define NW_WS_F   7968
#define NK2_TOT   8224        /* 32896 B */

// ---- device scratch ----
__device__ float g_cf[(size_t)ER_C * 32];
__device__ float g_cb[(size_t)ER_C * 32];
__device__ float g_epart[3][2][32][NB1];
__device__ float g_npart[2][32][NB2];
__device__ float g_escale[3][32], g_ebias[3][32];
__device__ float g_nscale[32],    g_nbias[32];

__device__ __forceinline__ float lrelu(float x) { return fmaxf(x, 0.01f * x); }

// ---- bf16 split helpers ----
__device__ __forceinline__ void bsplit(float v, unsigned short& h, unsigned short& l) {
    __nv_bfloat16 hb = __float2bfloat16_rn(v);
    float rest = v - __bfloat162float(hb);
    __nv_bfloat16 lb = __float2bfloat16_rn(rest);
    h = __bfloat16_as_ushort(hb);
    l = __bfloat16_as_ushort(lb);
}
// fast path: 2x cvt.rn.bf16x2 + 2 LOP + 2 FSUB; numerics identical to bsplit
__device__ __forceinline__ void split_pack2(float v0, float v1, uint32_t& hp, uint32_t& lp) {
    asm("cvt.rn.bf16x2.f32 %0, %1, %2;" : "=r"(hp) : "f"(v1), "f"(v0));
    float h0 = __uint_as_float(hp << 16);
    float h1 = __uint_as_float(hp & 0xFFFF0000u);
    float l0 = v0 - h0;
    float l1 = v1 - h1;
    asm("cvt.rn.bf16x2.f32 %0, %1, %2;" : "=r"(lp) : "f"(l1), "f"(l0));
}

// ---- HMMA m16n8k16 bf16 ----
__device__ __forceinline__ void mma4(float* c, const uint32_t* a, uint32_t b0, uint32_t b1) {
    asm volatile(
        "mma.sync.aligned.m16n8k16.row.col.f32.bf16.bf16.f32 "
        "{%0,%1,%2,%3}, {%4,%5,%6,%7}, {%8,%9}, {%0,%1,%2,%3};"
        : "+f"(c[0]), "+f"(c[1]), "+f"(c[2]), "+f"(c[3])
        : "r"(a[0]), "r"(a[1]), "r"(a[2]), "r"(a[3]), "r"(b0), "r"(b1));
}

// one K16-chunk of a 32xN32 layer; 3-product bf16 split
__device__ __forceinline__ void gemm_kc(const uint32_t* __restrict__ WFu,
        int blkH, int blkL, int kc,
        const uint32_t* aH, const uint32_t* aL, int lane, float* C)
{
    const uint4* ph = (const uint4*)(WFu + (blkH + kc) * 256 + lane * 4);
    const uint4* pl = (const uint4*)(WFu + (blkL + kc) * 256 + lane * 4);
    uint4 H0 = ph[0], H1 = ph[32];
    uint4 L0 = pl[0], L1 = pl[32];
#pragma unroll
    for (int mt = 0; mt < 2; mt++) {
        const uint32_t* ah = aH + mt * 4;
        const uint32_t* al = aL + mt * 4;
        float* c = C + mt * 16;
        mma4(c + 0,  ah, H0.x, H0.y); mma4(c + 0,  al, H0.x, H0.y); mma4(c + 0,  ah, L0.x, L0.y);
        mma4(c + 4,  ah, H0.z, H0.w); mma4(c + 4,  al, H0.z, H0.w); mma4(c + 4,  ah, L0.z, L0.w);
        mma4(c + 8,  ah, H1.x, H1.y); mma4(c + 8,  al, H1.x, H1.y); mma4(c + 8,  ah, L1.x, L1.y);
        mma4(c + 12, ah, H1.z, H1.w); mma4(c + 12, al, H1.z, H1.w); mma4(c + 12, ah, L1.z, L1.w);
    }
}

__device__ __forceinline__ void init_C(const float* bias, int t, float* C) {
#pragma unroll
    for (int nt = 0; nt < 4; nt++) {
        float b0 = bias[8 * nt + 2 * t];
        float b1 = bias[8 * nt + 2 * t + 1];
#pragma unroll
        for (int mt = 0; mt < 2; mt++) {
            C[mt*16 + nt*4 + 0] = b0; C[mt*16 + nt*4 + 1] = b1;
            C[mt*16 + nt*4 + 2] = b0; C[mt*16 + nt*4 + 3] = b1;
        }
    }
}

// relu + split C -> next-layer A frags (thread-local repack)
__device__ __forceinline__ void epi_split(const float* C, uint32_t* AH, uint32_t* AL) {
#pragma unroll
    for (int mt = 0; mt < 2; mt++)
#pragma unroll
        for (int kc = 0; kc < 2; kc++) {
            int j0 = 2 * kc, j1 = 2 * kc + 1;
            float v0 = lrelu(C[mt*16 + j0*4 + 0]), v1 = lrelu(C[mt*16 + j0*4 + 1]);
            float v2 = lrelu(C[mt*16 + j0*4 + 2]), v3 = lrelu(C[mt*16 + j0*4 + 3]);
            float u0 = lrelu(C[mt*16 + j1*4 + 0]), u1 = lrelu(C[mt*16 + j1*4 + 1]);
            float u2 = lrelu(C[mt*16 + j1*4 + 2]), u3 = lrelu(C[mt*16 + j1*4 + 3]);
            split_pack2(v0, v1, AH[kc*8 + mt*4 + 0], AL[kc*8 + mt*4 + 0]);
            split_pack2(v2, v3, AH[kc*8 + mt*4 + 1], AL[kc*8 + mt*4 + 1]);
            split_pack2(u0, u1, AH[kc*8 + mt*4 + 2], AL[kc*8 + mt*4 + 2]);
            split_pack2(u2, u3, AH[kc*8 + mt*4 + 3], AL[kc*8 + mt*4 + 3]);
        }
}

// ---------------- K1: HMMA edge chains, 4 tiles/block ----------------
__global__ __launch_bounds__(128, 3) void k_edge_tc(
    const float* __restrict__ x, float* __restrict__ dout,
    const float* __restrict__ eW1, const float* __restrict__ eb1,
    const float* __restrict__ eW2, const float* __restrict__ eb2,
    const float* __restrict__ eW3, const float* __restrict__ eb3)
{
    extern __shared__ float smf[];
    uint32_t* WFu = (uint32_t*)smf;
    const int tid = threadIdx.x, bid = blockIdx.x;
    const int lane = tid & 31, warp = tid >> 5;
    const int g = lane >> 2, t = lane & 3;
    const int rb0 = bid * (128 * TPB1);

    if (tid < 32) {
        float b1v = eb1[tid], wd = eW1[1024 + tid];
        smf[BIAS_F + tid]       = b1v;
        smf[BIAS_F + 32 + tid]  = b1v + wd;
        smf[BIAS_F + 64 + tid]  = b1v - wd;
        smf[BIAS_F + 96 + tid]  = eb2[tid];
        smf[BIAS_F + 128 + tid] = eb3[tid];
    }
    // stage x for all tiles + 1 boundary row (clamped)
    for (int idx = tid; idx < (128 * TPB1 + 1) * 16; idx += 128) {
        int row = rb0 + (idx >> 4);
        if (row > ROWS_C - 1) row = ROWS_C - 1;
        smf[XS_F + idx] = x[(size_t)row * 16 + (idx & 15)];
    }
    // weight B-fragment tables (14 blocks x 256 u32)
    for (int idx = tid; idx < 3584; idx += 128) {
        int blk = idx >> 8;
        int rem = idx & 255;
        int j4 = rem >> 7;
        int ln = (rem >> 2) & 31;
        int q  = rem & 3;
        int gg = ln >> 2, tt = ln & 3;
        int nt = 2 * j4 + (q >> 1);
        int rg = q & 1;
        int n  = 8 * nt + gg;
        int half, kc, which;
        if (blk < 2)       { which = 0; half = blk;          kc = 0; }
        else if (blk < 6)  { which = 1; half = (blk - 2) >> 1;  kc = (blk - 2) & 1; }
        else if (blk < 10) { which = 2; half = (blk - 6) >> 1;  kc = (blk - 6) & 1; }
        else               { which = 3; half = (blk - 10) >> 1; kc = (blk - 10) & 1; }
        int k0 = 16 * kc + 2 * tt + 8 * rg;
        float w0, w1;
        if (which == 0)      { w0 = eW1[k0*32+n] + eW1[(k0+16)*32+n];
                               w1 = eW1[(k0+1)*32+n] + eW1[(k0+17)*32+n]; }
        else if (which == 1) { w0 = eW1[k0*32+n]; w1 = eW1[(k0+1)*32+n]; }
        else if (which == 2) { w0 = eW2[k0*32+n]; w1 = eW2[(k0+1)*32+n]; }
        else                 { w0 = eW3[k0*32+n]; w1 = eW3[(k0+1)*32+n]; }
        unsigned short h0, l0, h1, l1;
        bsplit(w0, h0, l0); bsplit(w1, h1, l1);
        WFu[blk * 256 + j4 * 128 + ln * 4 + q] =
            (half == 0) ? ((uint32_t)h0 | ((uint32_t)h1 << 16))
                        : ((uint32_t)l0 | ((uint32_t)l1 << 16));
    }
    __syncthreads();

    const int wrow = warp * 32;
    float* bw = smf + BO_F + warp * 1152;

    for (int it = 0; it < TPB1; it++) {
        const int r0 = rb0 + it * 128;
        const int tile = bid * TPB1 + it;
        const int base_rl = it * 128 + wrow;

        uint32_t XcH[8], XcL[8], XnH[8], XnL[8];
#pragma unroll
        for (int mt = 0; mt < 2; mt++)
#pragma unroll
            for (int rr = 0; rr < 2; rr++) {
                int rl = base_rl + mt * 16 + rr * 8 + g;
                float2 vA = *(const float2*)(smf + XS_F + rl * 16 + 2 * t);
                float2 vB = *(const float2*)(smf + XS_F + rl * 16 + 2 * t + 8);
                split_pack2(vA.x, vA.y, XcH[mt*4 + rr],     XcL[mt*4 + rr]);
                split_pack2(vB.x, vB.y, XcH[mt*4 + 2 + rr], XcL[mt*4 + 2 + rr]);
                float2 nA = *(const float2*)(smf + XS_F + (rl + 1) * 16 + 2 * t);
                float2 nB = *(const float2*)(smf + XS_F + (rl + 1) * 16 + 2 * t + 8);
                split_pack2(nA.x, nA.y, XnH[mt*4 + rr],     XnL[mt*4 + rr]);
                split_pack2(nB.x, nB.y, XnH[mt*4 + 2 + rr], XnL[mt*4 + 2 + rr]);
            }

        uint32_t A2H[16], A2L[16];
        float C[32];

#pragma unroll
        for (int ch = 0; ch < 3; ch++) {
            init_C(smf + BIAS_F + ch * 32, t, C);
            if (ch == 0) {
                gemm_kc(WFu, BLK_WC_H, BLK_WC_L, 0, XcH, XcL, lane, C);
            } else if (ch == 1) {
                gemm_kc(WFu, BLK_W1_H, BLK_W1_L, 0, XnH, XnL, lane, C);
                gemm_kc(WFu, BLK_W1_H, BLK_W1_L, 1, XcH, XcL, lane, C);
            } else {
                gemm_kc(WFu, BLK_W1_H, BLK_W1_L, 0, XcH, XcL, lane, C);
                gemm_kc(WFu, BLK_W1_H, BLK_W1_L, 1, XnH, XnL, lane, C);
            }
            epi_split(C, A2H, A2L);
            init_C(smf + BIAS_F + 96, t, C);
            gemm_kc(WFu, BLK_W2_H, BLK_W2_L, 0, A2H,     A2L,     lane, C);
            gemm_kc(WFu, BLK_W2_H, BLK_W2_L, 1, A2H + 8, A2L + 8, lane, C);
            epi_split(C, A2H, A2L);
            init_C(smf + BIAS_F + 128, t, C);
            gemm_kc(WFu, BLK_W3_H, BLK_W3_L, 0, A2H,     A2L,     lane, C);
            gemm_kc(WFu, BLK_W3_H, BLK_W3_L, 1, A2H + 8, A2L + 8, lane, C);

            __syncwarp();
#pragma unroll
            for (int mt = 0; mt < 2; mt++)
#pragma unroll
                for (int nt = 0; nt < 4; nt++) {
                    int ra = mt * 16 + g, rbx = ra + 8;
                    *(float2*)(bw + ra * 36 + 8 * nt + 2 * t) =
                        make_float2(C[mt*16 + nt*4 + 0], C[mt*16 + nt*4 + 1]);
                    *(float2*)(bw + rbx * 36 + 8 * nt + 2 * t) =
                        make_float2(C[mt*16 + nt*4 + 2], C[mt*16 + nt*4 + 3]);
                }
            __syncwarp();
            {
                int rbase = r0 + wrow;
                float s = 0.f, q = 0.f;
#pragma unroll 4
                for (int rl = 0; rl < 32; rl++) {
                    float m = (ch == 0) ? 1.f : ((((rbase + rl) & 511) != 511) ? 1.f : 0.f);
                    float v = bw[rl * 36 + lane] * m;
                    s += v; q += v * v;
                }
                smf[WS_F + ((ch * 2 + 0) * 4 + warp) * 32 + lane] = s;
                smf[WS_F + ((ch * 2 + 1) * 4 + warp) * 32 + lane] = q;
            }
            if (ch == 0) {
#pragma unroll
                for (int i = 0; i < 8; i++) {
                    int rl = 4 * i + (lane >> 3);
                    int cc = (lane & 7) * 4;
                    float4 v = *(const float4*)(bw + rl * 36 + cc);
                    *(float4*)(dout + (size_t)(r0 + wrow + rl) * 32 + cc) = v;
                }
            } else {
                float* dst = (ch == 1) ? g_cf : g_cb;
#pragma unroll
                for (int i = 0; i < 8; i++) {
                    int rl = 4 * i + (lane >> 3);
                    int gr = r0 + wrow + rl;
                    if ((gr & 511) != 511) {
                        int e = gr - (gr >> 9);
                        int cc = (lane & 7) * 4;
                        float4 v = *(const float4*)(bw + rl * 36 + cc);
                        *(float4*)(dst + (size_t)e * 32 + cc) = v;
                    }
                }
            }
        }

        __syncthreads();
        for (int idx = tid; idx < 192; idx += 128) {
            int ch = idx / 64, st = (idx >> 5) & 1, c = idx & 31;
            float a = 0.f;
#pragma unroll
            for (int w = 0; w < 4; w++) a += smf[WS_F + ((ch * 2 + st) * 4 + w) * 32 + c];
            g_epart[ch][st][c][tile] = a;
        }
        __syncthreads();
    }
}

// ---------------- stats finalize ----------------
__global__ void k_fin_edge(const float* __restrict__ gamma, const float* __restrict__ beta) {
    int arr = blockIdx.x >> 5, c = blockIdx.x & 31;
    int tid = threadIdx.x;
    __shared__ double ss[256], sq[256];
    double sa = 0.0, sb2 = 0.0, qa = 0.0, qb = 0.0;
    const float* ps = &g_epart[arr][0][c][0];
    const float* pz = &g_epart[arr][1][c][0];
    for (int i = tid; i < NB1; i += 512) {
        sa += ps[i]; qa += pz[i];
        if (i + 256 < NB1) { sb2 += ps[i + 256]; qb += pz[i + 256]; }
    }
    ss[tid] = sa + sb2; sq[tid] = qa + qb;
    __syncthreads();
    for (int o = 128; o > 0; o >>= 1) {
        if (tid < o) { ss[tid] += ss[tid + o]; sq[tid] += sq[tid + o]; }
        __syncthreads();
    }
    if (tid == 0) {
        double M   = (arr == 0) ? (double)ROWS_C : (double)ER_C;
        double mu  = ss[0] / M;
        double var = sq[0] / M - mu * mu;
        double inv = 1.0 / sqrt(var + BN_EPS);
        g_escale[arr][c] = (float)((double)gamma[c] * inv);
        g_ebias [arr][c] = (float)((double)beta[c] - mu * (double)gamma[c] * inv);
    }
}

__global__ void k_fin_node(const float* __restrict__ gamma, const float* __restrict__ beta) {
    int c = blockIdx.x;
    int tid = threadIdx.x;
    __shared__ double ss[256], sq[256];
    double sa = 0.0, sb2 = 0.0, qa = 0.0, qb = 0.0;
    const float* ps = &g_npart[0][c][0];
    const float* pz = &g_npart[1][c][0];
    for (int i = tid; i < NB2; i += 512) {
        sa += ps[i]; qa += pz[i];
        if (i + 256 < NB2) { sb2 += ps[i + 256]; qb += pz[i + 256]; }
    }
    ss[tid] = sa + sb2; sq[tid] = qa + qb;
    __syncthreads();
    for (int o = 128; o > 0; o >>= 1) {
        if (tid < o) { ss[tid] += ss[tid + o]; sq[tid] += sq[tid + o]; }
        __syncthreads();
    }
    if (tid == 0) {
        double M   = (double)ROWS_C;
        double mu  = ss[0] / M;
        double var = sq[0] / M - mu * mu;
        double inv = 1.0 / sqrt(var + BN_EPS);
        g_nscale[c] = (float)((double)gamma[c] * inv);
        g_nbias [c] = (float)((double)beta[c] - mu * (double)gamma[c] * inv);
    }
}

// ---------------- K2: HMMA aggregate + node MLP, 4 tiles/block ----------------
__global__ __launch_bounds__(128, 4) void k_node_tc(
    float* __restrict__ dout,
    const float* __restrict__ nW1, const float* __restrict__ nb1,
    const float* __restrict__ nW2, const float* __restrict__ nb2,
    const float* __restrict__ nW3, const float* __restrict__ nb3)
{
    extern __shared__ float smf[];
    uint32_t* WFu = (uint32_t*)smf;
    const int tid = threadIdx.x, bid = blockIdx.x;
    const int lane = tid & 31, warp = tid >> 5;
    const int g = lane >> 2, t = lane & 3;

    if (tid < 32) {
        smf[NW_BIAS_F + tid]      = nb1[tid];
        smf[NW_BIAS_F + 32 + tid] = nb2[tid];
        smf[NW_BIAS_F + 64 + tid] = nb3[tid];
    }
    for (int i = tid; i < 192; i += 128) {
        int arr = i / 64, sb3 = (i >> 5) & 1, c = i & 31;
        smf[NW_SBE_F + i] = sb3 ? g_ebias[arr][c] : g_escale[arr][c];
    }
    for (int idx = tid; idx < 3072; idx += 128) {
        int blk = idx >> 8;
        int rem = idx & 255;
        int j4 = rem >> 7;
        int ln = (rem >> 2) & 31;
        int q  = rem & 3;
        int gg = ln >> 2, tt = ln & 3;
        int nt = 2 * j4 + (q >> 1);
        int rg = q & 1;
        int n  = 8 * nt + gg;
        int which = blk >> 2;
        int sub = blk & 3;
        int half = sub >> 1, kc = sub & 1;
        int k0 = 16 * kc + 2 * tt + 8 * rg;
        const float* W = (which == 0) ? nW1 : (which == 1) ? nW2 : nW3;
        float w0 = W[k0 * 32 + n], w1 = W[(k0 + 1) * 32 + n];
        unsigned short h0, l0, h1, l1;
        bsplit(w0, h0, l0); bsplit(w1, h1, l1);
        WFu[blk * 256 + j4 * 128 + ln * 4 + q] =
            (half == 0) ? ((uint32_t)h0 | ((uint32_t)h1 << 16))
                        : ((uint32_t)l0 | ((uint32_t)l1 << 16));
    }
    __syncthreads();

    const float* s0 = smf + NW_SBE_F;       const float* b0 = smf + NW_SBE_F + 32;
    const float* s1 = smf + NW_SBE_F + 64;  const float* b1 = smf + NW_SBE_F + 96;
    const float* s2 = smf + NW_SBE_F + 128; const float* b2 = smf + NW_SBE_F + 160;

    const int wrow = warp * 32;
    const int n0 = bid;                    // one sequence per block (512 rows)
    float* bw = smf + NW_BO_F + warp * 1152;
    const int c0 = 8 * t;

    for (int it = 0; it < TPB2; it++) {
        const int r0w = bid * (128 * TPB2) + it * 128 + wrow;
        const int tile = bid * TPB2 + it;

        // ---- aggregation into bounce ----
#pragma unroll
        for (int rr = 0; rr < 4; rr++) {
            int rl = 4 * g + rr;
            int r = r0w + rl;
            int tt2 = r & 511;
            float mf = (tt2 != 0)   ? 1.f : 0.f;
            float mb = (tt2 != 511) ? 1.f : 0.f;
            float a[8];

            const float4* ip = (const float4*)dout + (size_t)r * 8 + t * 2;
            float4 va = ip[0], vb = ip[1];
            a[0] = s0[c0+0]*va.x + b0[c0+0]; a[1] = s0[c0+1]*va.y + b0[c0+1];
            a[2] = s0[c0+2]*va.z + b0[c0+2]; a[3] = s0[c0+3]*va.w + b0[c0+3];
            a[4] = s0[c0+4]*vb.x + b0[c0+4]; a[5] = s0[c0+5]*vb.y + b0[c0+5];
            a[6] = s0[c0+6]*vb.z + b0[c0+6]; a[7] = s0[c0+7]*vb.w + b0[c0+7];
            {
                long e = (long)r - n0 - 1; if (e < 0) e = 0;
                const float4* fp = (const float4*)(g_cf + (size_t)e * 32 + c0);
                float4 fa = fp[0], fb = fp[1];
                a[0] += mf * (s1[c0+0]*fa.x + b1[c0+0]);
                a[1] += mf * (s1[c0+1]*fa.y + b1[c0+1]);
                a[2] += mf * (s1[c0+2]*fa.z + b1[c0+2]);
                a[3] += mf * (s1[c0+3]*fa.w + b1[c0+3]);
                a[4] += mf * (s1[c0+4]*fb.x + b1[c0+4]);
                a[5] += mf * (s1[c0+5]*fb.y + b1[c0+5]);
                a[6] += mf * (s1[c0+6]*fb.z + b1[c0+6]);
                a[7] += mf * (s1[c0+7]*fb.w + b1[c0+7]);
            }
            {
                long e = (long)r - n0; if (e > ER_C - 1) e = ER_C - 1;
                const float4* bp = (const float4*)(g_cb + (size_t)e * 32 + c0);
                float4 ba = bp[0], bb = bp[1];
                a[0] += mb * (s2[c0+0]*ba.x + b2[c0+0]);
                a[1] += mb * (s2[c0+1]*ba.y + b2[c0+1]);
                a[2] += mb * (s2[c0+2]*ba.z + b2[c0+2]);
                a[3] += mb * (s2[c0+3]*ba.w + b2[c0+3]);
                a[4] += mb * (s2[c0+4]*bb.x + b2[c0+4]);
                a[5] += mb * (s2[c0+5]*bb.y + b2[c0+5]);
                a[6] += mb * (s2[c0+6]*bb.z + b2[c0+6]);
                a[7] += mb * (s2[c0+7]*bb.w + b2[c0+7]);
            }
            *(float4*)(bw + rl * 36 + c0)     = make_float4(a[0], a[1], a[2], a[3]);
            *(float4*)(bw + rl * 36 + c0 + 4) = make_float4(a[4], a[5], a[6], a[7]);
        }
        __syncwarp();

        uint32_t AH[16], AL[16];
#pragma unroll
        for (int mt = 0; mt < 2; mt++)
#pragma unroll
            for (int rr = 0; rr < 2; rr++) {
                int rl = mt * 16 + rr * 8 + g;
#pragma unroll
                for (int kc = 0; kc < 2; kc++) {
                    float2 vA = *(const float2*)(bw + rl * 36 + 16 * kc + 2 * t);
                    float2 vB = *(const float2*)(bw + rl * 36 + 16 * kc + 2 * t + 8);
                    split_pack2(vA.x, vA.y, AH[kc*8 + mt*4 + rr],     AL[kc*8 + mt*4 + rr]);
                    split_pack2(vB.x, vB.y, AH[kc*8 + mt*4 + 2 + rr], AL[kc*8 + mt*4 + 2 + rr]);
                }
            }

        float C[32];
        init_C(smf + NW_BIAS_F, t, C);
        gemm_kc(WFu, NBLK_W1_H, NBLK_W1_L, 0, AH,     AL,     lane, C);
        gemm_kc(WFu, NBLK_W1_H, NBLK_W1_L, 1, AH + 8, AL + 8, lane, C);
        epi_split(C, AH, AL);
        init_C(smf + NW_BIAS_F + 32, t, C);
        gemm_kc(WFu, NBLK_W2_H, NBLK_W2_L, 0, AH,     AL,     lane, C);
        gemm_kc(WFu, NBLK_W2_H, NBLK_W2_L, 1, AH + 8, AL + 8, lane, C);
        epi_split(C, AH, AL);
        init_C(smf + NW_BIAS_F + 64, t, C);
        gemm_kc(WFu, NBLK_W3_H, NBLK_W3_L, 0, AH,     AL,     lane, C);
        gemm_kc(WFu, NBLK_W3_H, NBLK_W3_L, 1, AH + 8, AL + 8, lane, C);

        __syncwarp();
#pragma unroll
        for (int mt = 0; mt < 2; mt++)
#pragma unroll
            for (int nt = 0; nt < 4; nt++) {
                int ra = mt * 16 + g, rbx = ra + 8;
                *(float2*)(bw + ra * 36 + 8 * nt + 2 * t) =
                    make_float2(C[mt*16 + nt*4 + 0], C[mt*16 + nt*4 + 1]);
                *(float2*)(bw + rbx * 36 + 8 * nt + 2 * t) =
                    make_float2(C[mt*16 + nt*4 + 2], C[mt*16 + nt*4 + 3]);
            }
        __syncwarp();
        {
            float s = 0.f, q = 0.f;
#pragma unroll 4
            for (int rl = 0; rl < 32; rl++) {
                float v = bw[rl * 36 + lane];
                s += v; q += v * v;
            }
            smf[NW_WS_F + (0 * 4 + warp) * 32 + lane] = s;
            smf[NW_WS_F + (1 * 4 + warp) * 32 + lane] = q;
        }
#pragma unroll
        for (int i = 0; i < 8; i++) {
            int rl = 4 * i + (lane >> 3);
            int cc = (lane & 7) * 4;
            float4 v = *(const float4*)(bw + rl * 36 + cc);
            *(float4*)(dout + (size_t)(r0w + rl) * 32 + cc) = v;
        }

        __syncthreads();
        if (tid < 64) {
            int st = tid >> 5, c = tid & 31;
            float a = 0.f;
#pragma unroll
            for (int w = 0; w < 4; w++) a += smf[NW_WS_F + (st * 4 + w) * 32 + c];
            g_npart[st][c][tile] = a;
        }
        __syncthreads();
    }
}

// ---------------- K3: normalize in place ----------------
__global__ __launch_bounds__(256) void k_final(float* __restrict__ dout) {
    __shared__ float sc[32], bi[32];
    int tid = threadIdx.x;
    if (tid < 32) { sc[tid] = g_nscale[tid]; bi[tid] = g_nbias[tid]; }
    __syncthreads();
    int lane = tid & 31;
    int s = lane & 3;
    int r = (blockIdx.x * 256 + tid) >> 2;
    int c0 = s * 8;
    float4* D4 = reinterpret_cast<float4*>(dout);
    float4 va = D4[(size_t)r * 8 + s * 2];
    float4 vb = D4[(size_t)r * 8 + s * 2 + 1];
    va.x = va.x * sc[c0 + 0] + bi[c0 + 0]; va.y = va.y * sc[c0 + 1] + bi[c0 + 1];
    va.z = va.z * sc[c0 + 2] + bi[c0 + 2]; va.w = va.w * sc[c0 + 3] + bi[c0 + 3];
    vb.x = vb.x * sc[c0 + 4] + bi[c0 + 4]; vb.y = vb.y * sc[c0 + 5] + bi[c0 + 5];
    vb.z = vb.z * sc[c0 + 6] + bi[c0 + 6]; vb.w = vb.w * sc[c0 + 7] + bi[c0 + 7];
    D4[(size_t)r * 8 + s * 2]     = va;
    D4[(size_t)r * 8 + s * 2 + 1] = vb;
}

// ---------------- launch ----------------
extern "C" void kernel_launch(void* const* d_in, const int* in_sizes, int n_in,
                              void* d_out, int out_size)
{
    const float* x    = (const float*)d_in[0];
    const float* eW1  = (const float*)d_in[1];
    const float* eb1  = (const float*)d_in[2];
    const float* eW2  = (const float*)d_in[3];
    const float* eb2  = (const float*)d_in[4];
    const float* eW3  = (const float*)d_in[5];
    const float* eb3  = (const float*)d_in[6];
    const float* eg   = (const float*)d_in[7];
    const float* ebt  = (const float*)d_in[8];
    const float* nW1  = (const float*)d_in[9];
    const float* nb1  = (const float*)d_in[10];
    const float* nW2  = (const float*)d_in[11];
    const float* nb2  = (const float*)d_in[12];
    const float* nW3  = (const float*)d_in[13];
    const float* nb3  = (const float*)d_in[14];
    const float* ng   = (const float*)d_in[15];
    const float* nbt  = (const float*)d_in[16];
    float* out = (float*)d_out;

    cudaFuncSetAttribute(k_edge_tc, cudaFuncAttributeMaxDynamicSharedMemorySize, K1_TOT * 4);
    cudaFuncSetAttribute(k_node_tc, cudaFuncAttributeMaxDynamicSharedMemorySize, NK2_TOT * 4);

    k_edge_tc<<<GRID1, 128, K1_TOT * 4>>>(x, out, eW1, eb1, eW2, eb2, eW3, eb3);
    k_fin_edge<<<96, 256>>>(eg, ebt);
    k_node_tc<<<GRID2, 128, NK2_TOT * 4>>>(out, nW1, nb1, nW2, nb2, nW3, nb3);
    k_fin_node<<<32, 256>>>(ng, nbt);
    k_final<<<ROWS_C * 4 / 256, 256>>>(out);
}